// round 9
// baseline (speedup 1.0000x reference)
#include <cuda_runtime.h>
#include <cuda_fp16.h>

#define NN 100000
#define EE 1600000
#define E2 (EE + NN)
#define GG 64
#define HID 64
#define EDIM 16
#define OUTD 128

// ---------------- scratch (device globals; no allocation) ----------------
__device__ float d_cnt[NN];
__device__ float d_loop[NN * EDIM];
__device__ __half d_xl[NN * HID];
__device__ __half d_xr[NN * HID];
__device__ float d_acc[NN * HID];
__device__ float d_den[NN * 4];
__device__ float d_g[GG * HID];
__device__ float d_gc[GG];
__device__ __half2 d_ep0[(size_t)E2 * 32];   // layer-0 ea @ We (fp16)
__device__ __half2 d_ep1[(size_t)E2 * 32];   // layer-1 ea @ We (fp16)

__device__ __forceinline__ void red4(float* p, float a, float b, float c, float d) {
    asm volatile("red.global.add.v4.f32 [%0], {%1,%2,%3,%4};"
                 :: "l"(p), "f"(a), "f"(b), "f"(c), "f"(d) : "memory");
}
__device__ __forceinline__ void red2(float* p, float a, float b) {
    asm volatile("red.global.add.v2.f32 [%0], {%1,%2};"
                 :: "l"(p), "f"(a), "f"(b) : "memory");
}

// ---------------- self-loop mean edge attr (sum; division folded into ep_k) ----------------
__global__ void loop_accum_k(const int* __restrict__ ei, const float* __restrict__ ea) {
    int e = blockIdx.x * blockDim.x + threadIdx.x;
    if (e >= EE) return;
    int dst = ei[EE + e];
    const float4* a4 = reinterpret_cast<const float4*>(ea + (size_t)e * EDIM);
    float* o = d_loop + (size_t)dst * EDIM;
#pragma unroll
    for (int i = 0; i < 4; i++) {
        float4 v = a4[i];
        red4(o + 4 * i, v.x, v.y, v.z, v.w);
    }
    atomicAdd(&d_cnt[dst], 1.0f);
}

// ---------------- edge projection precompute: ep = ea @ We (fp16 out) ----------------
// Warp handles an edge pair; self-loop attrs normalized by cnt inline.
__global__ void ep_k(const float* __restrict__ ea, const float* __restrict__ We,
                     __half2* __restrict__ ep) {
    const unsigned F = 0xffffffffu;
    int lane = threadIdx.x & 31;
    float2 w[EDIM];
    const float2* We2 = reinterpret_cast<const float2*>(We);
#pragma unroll
    for (int k = 0; k < EDIM; k++) w[k] = We2[k * 32 + lane];

    int wid = (blockIdx.x * blockDim.x + threadIdx.x) >> 5;
    int nwarp = (gridDim.x * blockDim.x) >> 5;

    for (int i = wid; i < E2 / 2; i += nwarp) {
        int e0 = 2 * i;
        float av;
        if (e0 < EE) {
            av = ea[(size_t)e0 * EDIM + lane];
        } else {
            int n0 = e0 - EE;
            int n = n0 + (lane >> 4);
            av = d_loop[(size_t)n0 * EDIM + lane] / fmaxf(d_cnt[n], 1.0f);
        }
        float ex0 = 0.0f, ey0 = 0.0f, ex1 = 0.0f, ey1 = 0.0f;
#pragma unroll
        for (int k = 0; k < EDIM; k++) {
            float a0 = __shfl_sync(F, av, k);
            float a1 = __shfl_sync(F, av, k + 16);
            ex0 += a0 * w[k].x;
            ey0 += a0 * w[k].y;
            ex1 += a1 * w[k].x;
            ey1 += a1 * w[k].y;
        }
        ep[(size_t)e0 * 32 + lane] = __floats2half2_rn(ex0, ey0);
        ep[(size_t)(e0 + 1) * 32 + lane] = __floats2half2_rn(ex1, ey1);
    }
}

// ---------------- node projections (layer 0), fp16 outputs ----------------
__global__ void node_proj_k(const float* __restrict__ x,
                            const float* __restrict__ Wl, const float* __restrict__ bl,
                            const float* __restrict__ Wr, const float* __restrict__ br) {
    __shared__ float sWl[64 * 64];
    __shared__ float sWr[64 * 64];
    __shared__ float sx[16 * 64];
    for (int i = threadIdx.x; i < 64 * 16; i += blockDim.x) {
        reinterpret_cast<float4*>(sWl)[i] = reinterpret_cast<const float4*>(Wl)[i];
        reinterpret_cast<float4*>(sWr)[i] = reinterpret_cast<const float4*>(Wr)[i];
    }
    int c  = threadIdx.x & 63;
    int rl = threadIdx.x >> 6;
    float blc = bl[c], brc = br[c];
    for (int base = blockIdx.x * 16; base < NN; base += gridDim.x * 16) {
        __syncthreads();
        for (int i = threadIdx.x; i < 16 * 16; i += 256) {
            int r = base + (i >> 4);
            reinterpret_cast<float4*>(sx)[i] = (r < NN)
                ? reinterpret_cast<const float4*>(x)[(size_t)r * 16 + (i & 15)]
                : make_float4(0.f, 0.f, 0.f, 0.f);
        }
        __syncthreads();
        float s0 = blc, s1 = blc, s2 = blc, s3 = blc;
        float t0 = brc, t1 = brc, t2 = brc, t3 = brc;
        const float* xrow = sx + rl * 4 * 64;
#pragma unroll
        for (int k = 0; k < 64; k++) {
            float wl = sWl[k * 64 + c];
            float wr = sWr[k * 64 + c];
            float x0 = xrow[0 * 64 + k];
            float x1 = xrow[1 * 64 + k];
            float x2 = xrow[2 * 64 + k];
            float x3 = xrow[3 * 64 + k];
            s0 += x0 * wl; t0 += x0 * wr;
            s1 += x1 * wl; t1 += x1 * wr;
            s2 += x2 * wl; t2 += x2 * wr;
            s3 += x3 * wl; t3 += x3 * wr;
        }
        int r0 = base + rl * 4;
        if (r0 + 0 < NN) { d_xl[(size_t)(r0 + 0) * 64 + c] = __float2half(s0); d_xr[(size_t)(r0 + 0) * 64 + c] = __float2half(t0); }
        if (r0 + 1 < NN) { d_xl[(size_t)(r0 + 1) * 64 + c] = __float2half(s1); d_xr[(size_t)(r0 + 1) * 64 + c] = __float2half(t1); }
        if (r0 + 2 < NN) { d_xl[(size_t)(r0 + 2) * 64 + c] = __float2half(s2); d_xr[(size_t)(r0 + 2) * 64 + c] = __float2half(t2); }
        if (r0 + 3 < NN) { d_xl[(size_t)(r0 + 3) * 64 + c] = __float2half(s3); d_xr[(size_t)(r0 + 3) * 64 + c] = __float2half(t3); }
    }
}

// ---------------- node projection (layer 1): fuses layer-0 finalize ----------------
__global__ void node_proj_fused_k(const float* __restrict__ bias0,
                                  const float* __restrict__ Wl, const float* __restrict__ bl,
                                  const float* __restrict__ Wr, const float* __restrict__ br) {
    __shared__ float sWl[64 * 64];
    __shared__ float sWr[64 * 64];
    __shared__ float sx[16 * 64];
    for (int i = threadIdx.x; i < 64 * 16; i += blockDim.x) {
        reinterpret_cast<float4*>(sWl)[i] = reinterpret_cast<const float4*>(Wl)[i];
        reinterpret_cast<float4*>(sWr)[i] = reinterpret_cast<const float4*>(Wr)[i];
    }
    int c  = threadIdx.x & 63;
    int rl = threadIdx.x >> 6;
    float blc = bl[c], brc = br[c];
    for (int base = blockIdx.x * 16; base < NN; base += gridDim.x * 16) {
        __syncthreads();
        for (int i = threadIdx.x; i < 16 * 16; i += 256) {
            int r = base + (i >> 4);
            int part = i & 15;
            float4 v = make_float4(0.f, 0.f, 0.f, 0.f);
            if (r < NN) {
                float inv = 1.0f / d_den[r * 4 + (part >> 2)];
                float4 a = reinterpret_cast<const float4*>(d_acc)[(size_t)r * 16 + part];
                float4 b = reinterpret_cast<const float4*>(bias0)[part];
                v.x = fmaxf(a.x * inv + b.x, 0.0f);
                v.y = fmaxf(a.y * inv + b.y, 0.0f);
                v.z = fmaxf(a.z * inv + b.z, 0.0f);
                v.w = fmaxf(a.w * inv + b.w, 0.0f);
            }
            reinterpret_cast<float4*>(sx)[i] = v;
        }
        __syncthreads();
        float s0 = blc, s1 = blc, s2 = blc, s3 = blc;
        float t0 = brc, t1 = brc, t2 = brc, t3 = brc;
        const float* xrow = sx + rl * 4 * 64;
#pragma unroll
        for (int k = 0; k < 64; k++) {
            float wl = sWl[k * 64 + c];
            float wr = sWr[k * 64 + c];
            float x0 = xrow[0 * 64 + k];
            float x1 = xrow[1 * 64 + k];
            float x2 = xrow[2 * 64 + k];
            float x3 = xrow[3 * 64 + k];
            s0 += x0 * wl; t0 += x0 * wr;
            s1 += x1 * wl; t1 += x1 * wr;
            s2 += x2 * wl; t2 += x2 * wr;
            s3 += x3 * wl; t3 += x3 * wr;
        }
        int r0 = base + rl * 4;
        if (r0 + 0 < NN) { d_xl[(size_t)(r0 + 0) * 64 + c] = __float2half(s0); d_xr[(size_t)(r0 + 0) * 64 + c] = __float2half(t0); }
        if (r0 + 1 < NN) { d_xl[(size_t)(r0 + 1) * 64 + c] = __float2half(s1); d_xr[(size_t)(r0 + 1) * 64 + c] = __float2half(t1); }
        if (r0 + 2 < NN) { d_xl[(size_t)(r0 + 2) * 64 + c] = __float2half(s2); d_xr[(size_t)(r0 + 2) * 64 + c] = __float2half(t2); }
        if (r0 + 3 < NN) { d_xl[(size_t)(r0 + 3) * 64 + c] = __float2half(s3); d_xr[(size_t)(r0 + 3) * 64 + c] = __float2half(t3); }
    }
}

// ---------------- edge pass: 4 edges per warp iteration ----------------
// Quad (4i..4i+3); lane l owns channels {2l,2l+1}; head = lane>>3.
// 8 gathers + 4 ep loads + int4 indices all in flight -> 2x MLP vs pair version.
// EE and NN divisible by 4 -> quads never straddle the self-loop boundary.
__global__ __launch_bounds__(256)
void edge_pass_k(const int* __restrict__ ei, const float* __restrict__ att,
                 const __half2* __restrict__ ep) {
    const unsigned F = 0xffffffffu;
    int lane = threadIdx.x & 31;
    float2 at = reinterpret_cast<const float2*>(att)[lane];

    int wid = (blockIdx.x * blockDim.x + threadIdx.x) >> 5;
    int nwarp = (gridDim.x * blockDim.x) >> 5;
    const __half2* xl2p = reinterpret_cast<const __half2*>(d_xl);
    const __half2* xr2p = reinterpret_cast<const __half2*>(d_xr);

    for (int i = wid; i < E2 / 4; i += nwarp) {
        int e0 = 4 * i;
        int4 sq, dq;
        if (e0 < EE) {
            sq = *reinterpret_cast<const int4*>(ei + e0);
            dq = *reinterpret_cast<const int4*>(ei + EE + e0);
        } else {
            int n = e0 - EE;
            sq = make_int4(n, n + 1, n + 2, n + 3);
            dq = sq;
        }
        float2 ep0 = __half22float2(ep[(size_t)(e0 + 0) * 32 + lane]);
        float2 ep1 = __half22float2(ep[(size_t)(e0 + 1) * 32 + lane]);
        float2 ep2 = __half22float2(ep[(size_t)(e0 + 2) * 32 + lane]);
        float2 ep3 = __half22float2(ep[(size_t)(e0 + 3) * 32 + lane]);
        float2 xl0 = __half22float2(xl2p[(size_t)sq.x * 32 + lane]);
        float2 xl1 = __half22float2(xl2p[(size_t)sq.y * 32 + lane]);
        float2 xl2 = __half22float2(xl2p[(size_t)sq.z * 32 + lane]);
        float2 xl3 = __half22float2(xl2p[(size_t)sq.w * 32 + lane]);
        float2 xr0 = __half22float2(xr2p[(size_t)dq.x * 32 + lane]);
        float2 xr1 = __half22float2(xr2p[(size_t)dq.y * 32 + lane]);
        float2 xr2 = __half22float2(xr2p[(size_t)dq.z * 32 + lane]);
        float2 xr3 = __half22float2(xr2p[(size_t)dq.w * 32 + lane]);

        float m0x = xl0.x + xr0.x + ep0.x, m0y = xl0.y + xr0.y + ep0.y;
        float m1x = xl1.x + xr1.x + ep1.x, m1y = xl1.y + xr1.y + ep1.y;
        float m2x = xl2.x + xr2.x + ep2.x, m2y = xl2.y + xr2.y + ep2.y;
        float m3x = xl3.x + xr3.x + ep3.x, m3y = xl3.y + xr3.y + ep3.y;
        m0x = (m0x > 0.f) ? m0x : 0.2f * m0x;  m0y = (m0y > 0.f) ? m0y : 0.2f * m0y;
        m1x = (m1x > 0.f) ? m1x : 0.2f * m1x;  m1y = (m1y > 0.f) ? m1y : 0.2f * m1y;
        m2x = (m2x > 0.f) ? m2x : 0.2f * m2x;  m2y = (m2y > 0.f) ? m2y : 0.2f * m2y;
        m3x = (m3x > 0.f) ? m3x : 0.2f * m3x;  m3y = (m3y > 0.f) ? m3y : 0.2f * m3y;
        float s0 = m0x * at.x + m0y * at.y;
        float s1 = m1x * at.x + m1y * at.y;
        float s2 = m2x * at.x + m2y * at.y;
        float s3 = m3x * at.x + m3y * at.y;
        s0 += __shfl_xor_sync(F, s0, 1); s1 += __shfl_xor_sync(F, s1, 1);
        s2 += __shfl_xor_sync(F, s2, 1); s3 += __shfl_xor_sync(F, s3, 1);
        s0 += __shfl_xor_sync(F, s0, 2); s1 += __shfl_xor_sync(F, s1, 2);
        s2 += __shfl_xor_sync(F, s2, 2); s3 += __shfl_xor_sync(F, s3, 2);
        s0 += __shfl_xor_sync(F, s0, 4); s1 += __shfl_xor_sync(F, s1, 4);
        s2 += __shfl_xor_sync(F, s2, 4); s3 += __shfl_xor_sync(F, s3, 4);
        float z0 = __expf(s0);   // softmax without max-shift (scores O(1))
        float z1 = __expf(s1);
        float z2 = __expf(s2);
        float z3 = __expf(s3);

        red2(d_acc + (size_t)dq.x * 64 + 2 * lane, z0 * xl0.x, z0 * xl0.y);
        red2(d_acc + (size_t)dq.y * 64 + 2 * lane, z1 * xl1.x, z1 * xl1.y);
        red2(d_acc + (size_t)dq.z * 64 + 2 * lane, z2 * xl2.x, z2 * xl2.y);
        red2(d_acc + (size_t)dq.w * 64 + 2 * lane, z3 * xl3.x, z3 * xl3.y);
        if ((lane & 7) == 0) {
            int h = lane >> 3;
            atomicAdd(&d_den[(size_t)dq.x * 4 + h], z0);
            atomicAdd(&d_den[(size_t)dq.y * 4 + h], z1);
            atomicAdd(&d_den[(size_t)dq.z * 4 + h], z2);
            atomicAdd(&d_den[(size_t)dq.w * 4 + h], z3);
        }
    }
}

// ---------------- finalize layer 1 fused with global mean pool ----------------
__global__ void node_out_pool_k(const float* __restrict__ bias, const int* __restrict__ batch) {
    int t = blockIdx.x * blockDim.x + threadIdx.x;
    if (t >= NN * 16) return;
    int node = t >> 4;
    int part = t & 15;
    float inv = 1.0f / d_den[node * 4 + (part >> 2)];
    float4 a = reinterpret_cast<const float4*>(d_acc)[t];
    float4 b = reinterpret_cast<const float4*>(bias)[part];
    float vx = fmaxf(a.x * inv + b.x, 0.0f);
    float vy = fmaxf(a.y * inv + b.y, 0.0f);
    float vz = fmaxf(a.z * inv + b.z, 0.0f);
    float vw = fmaxf(a.w * inv + b.w, 0.0f);
    int g = batch[node];
    red4(d_g + g * 64 + part * 4, vx, vy, vz, vw);
    if (part == 0) atomicAdd(&d_gc[g], 1.0f);
}

// ---------------- MLP head ----------------
__global__ void mlp_k(const float* __restrict__ W1, const float* __restrict__ b1,
                      const float* __restrict__ W2, const float* __restrict__ b2,
                      float* __restrict__ out) {
    __shared__ float gx[64];
    __shared__ float hh[128];
    int g = blockIdx.x;
    int t = threadIdx.x;
    if (t < 64) gx[t] = d_g[g * 64 + t] / fmaxf(d_gc[g], 1.0f);
    __syncthreads();
    float s = b1[t];
#pragma unroll
    for (int k = 0; k < 64; k++) s += gx[k] * W1[k * 128 + t];
    hh[t] = fmaxf(s, 0.0f);
    __syncthreads();
    float o = b2[t];
#pragma unroll
    for (int k = 0; k < 128; k++) o += hh[k] * W2[k * 128 + t];
    out[g * 128 + t] = o;
}

// ---------------- launch ----------------
extern "C" void kernel_launch(void* const* d_in, const int* in_sizes, int n_in,
                              void* d_out, int out_size) {
    const float* x0     = (const float*)d_in[0];
    const int*   ei     = (const int*)d_in[1];
    const float* ea     = (const float*)d_in[2];
    const int*   batch  = (const int*)d_in[3];
    const float* l0Wl   = (const float*)d_in[4];
    const float* l0bl   = (const float*)d_in[5];
    const float* l0Wr   = (const float*)d_in[6];
    const float* l0br   = (const float*)d_in[7];
    const float* l0We   = (const float*)d_in[8];
    const float* l0att  = (const float*)d_in[9];
    const float* l0bias = (const float*)d_in[10];
    const float* l1Wl   = (const float*)d_in[11];
    const float* l1bl   = (const float*)d_in[12];
    const float* l1Wr   = (const float*)d_in[13];
    const float* l1br   = (const float*)d_in[14];
    const float* l1We   = (const float*)d_in[15];
    const float* l1att  = (const float*)d_in[16];
    const float* l1bias = (const float*)d_in[17];
    const float* W1     = (const float*)d_in[18];
    const float* b1     = (const float*)d_in[19];
    const float* W2     = (const float*)d_in[20];
    const float* b2     = (const float*)d_in[21];
    float* out = (float*)d_out;

    static cudaStream_t s2;
    static cudaEvent_t evFork, evJoin;
    static bool inited = false;
    if (!inited) {
        cudaStreamCreateWithFlags(&s2, cudaStreamNonBlocking);
        cudaEventCreateWithFlags(&evFork, cudaEventDisableTiming);
        cudaEventCreateWithFlags(&evJoin, cudaEventDisableTiming);
        inited = true;
    }

    void *pcnt, *ploop, *pacc, *pden, *pg, *pgc, *pep0, *pep1;
    cudaGetSymbolAddress(&pcnt, d_cnt);
    cudaGetSymbolAddress(&ploop, d_loop);
    cudaGetSymbolAddress(&pacc, d_acc);
    cudaGetSymbolAddress(&pden, d_den);
    cudaGetSymbolAddress(&pg, d_g);
    cudaGetSymbolAddress(&pgc, d_gc);
    cudaGetSymbolAddress(&pep0, d_ep0);
    cudaGetSymbolAddress(&pep1, d_ep1);

    cudaMemsetAsync(pcnt, 0, NN * sizeof(float));
    cudaMemsetAsync(ploop, 0, NN * EDIM * sizeof(float));
    cudaMemsetAsync(pg, 0, GG * HID * sizeof(float));
    cudaMemsetAsync(pgc, 0, GG * sizeof(float));

    loop_accum_k<<<(EE + 255) / 256, 256>>>(ei, ea);

    // fork: layer-1 ep precompute runs concurrently with layer-0 work
    cudaEventRecord(evFork, 0);
    cudaStreamWaitEvent(s2, evFork, 0);
    ep_k<<<2048, 256, 0, s2>>>(ea, l1We, d_ep1);
    cudaEventRecord(evJoin, s2);

    // ---- layer 0 ----
    ep_k<<<2048, 256>>>(ea, l0We, d_ep0);
    node_proj_k<<<2048, 256>>>(x0, l0Wl, l0bl, l0Wr, l0br);
    cudaMemsetAsync(pacc, 0, (size_t)NN * HID * sizeof(float));
    cudaMemsetAsync(pden, 0, (size_t)NN * 4 * sizeof(float));
    edge_pass_k<<<2048, 256>>>(ei, l0att, d_ep0);

    // ---- layer 1 (layer-0 finalize fused into projection) ----
    node_proj_fused_k<<<2048, 256>>>(l0bias, l1Wl, l1bl, l1Wr, l1br);
    cudaMemsetAsync(pacc, 0, (size_t)NN * HID * sizeof(float));
    cudaMemsetAsync(pden, 0, (size_t)NN * 4 * sizeof(float));
    cudaStreamWaitEvent(0, evJoin, 0);   // join before consuming d_ep1
    edge_pass_k<<<2048, 256>>>(ei, l1att, d_ep1);
    node_out_pool_k<<<(NN * 16 + 255) / 256, 256>>>(l1bias, batch);

    // ---- MLP ----
    mlp_k<<<GG, OUTD>>>(W1, b1, W2, b2, out);
}

// round 10
// speedup vs baseline: 5.5945x; 5.5945x over previous
#include <cuda_runtime.h>
#include <cuda_fp16.h>

#define NN 100000
#define EE 1600000
#define E2 (EE + NN)
#define GG 64
#define HID 64
#define EDIM 16
#define OUTD 128

// ---------------- scratch (device globals; no allocation) ----------------
__device__ float d_cnt[NN];
__device__ float d_loop[NN * EDIM];
__device__ __half d_xl[NN * HID];
__device__ __half d_xr[NN * HID];
__device__ float d_acc[NN * HID];
__device__ float d_den[NN * 4];
__device__ float d_g[GG * HID];
__device__ float d_gc[GG];
__device__ __half2 d_ep[(size_t)E2 * 32];   // ea @ We (fp16)

__device__ __forceinline__ void red4(float* p, float a, float b, float c, float d) {
    asm volatile("red.global.add.v4.f32 [%0], {%1,%2,%3,%4};"
                 :: "l"(p), "f"(a), "f"(b), "f"(c), "f"(d) : "memory");
}
__device__ __forceinline__ void red2(float* p, float a, float b) {
    asm volatile("red.global.add.v2.f32 [%0], {%1,%2};"
                 :: "l"(p), "f"(a), "f"(b) : "memory");
}

// ---------------- self-loop mean edge attr (sum; division folded into ep_k) ----------------
__global__ void loop_accum_k(const int* __restrict__ ei, const float* __restrict__ ea) {
    int e = blockIdx.x * blockDim.x + threadIdx.x;
    if (e >= EE) return;
    int dst = ei[EE + e];
    const float4* a4 = reinterpret_cast<const float4*>(ea + (size_t)e * EDIM);
    float* o = d_loop + (size_t)dst * EDIM;
#pragma unroll
    for (int i = 0; i < 4; i++) {
        float4 v = a4[i];
        red4(o + 4 * i, v.x, v.y, v.z, v.w);
    }
    atomicAdd(&d_cnt[dst], 1.0f);
}

// ---------------- edge projection precompute: ep = ea @ We (fp16 out) ----------------
// Warp handles an edge pair; self-loop attrs normalized by cnt inline.
__global__ void ep_k(const float* __restrict__ ea, const float* __restrict__ We) {
    const unsigned F = 0xffffffffu;
    int lane = threadIdx.x & 31;
    float2 w[EDIM];
    const float2* We2 = reinterpret_cast<const float2*>(We);
#pragma unroll
    for (int k = 0; k < EDIM; k++) w[k] = We2[k * 32 + lane];

    int wid = (blockIdx.x * blockDim.x + threadIdx.x) >> 5;
    int nwarp = (gridDim.x * blockDim.x) >> 5;

    for (int i = wid; i < E2 / 2; i += nwarp) {
        int e0 = 2 * i;
        float av;
        if (e0 < EE) {
            av = ea[(size_t)e0 * EDIM + lane];
        } else {
            int n0 = e0 - EE;
            int n = n0 + (lane >> 4);
            av = d_loop[(size_t)n0 * EDIM + lane] / fmaxf(d_cnt[n], 1.0f);
        }
        float ex0 = 0.0f, ey0 = 0.0f, ex1 = 0.0f, ey1 = 0.0f;
#pragma unroll
        for (int k = 0; k < EDIM; k++) {
            float a0 = __shfl_sync(F, av, k);
            float a1 = __shfl_sync(F, av, k + 16);
            ex0 += a0 * w[k].x;
            ey0 += a0 * w[k].y;
            ex1 += a1 * w[k].x;
            ey1 += a1 * w[k].y;
        }
        d_ep[(size_t)e0 * 32 + lane] = __floats2half2_rn(ex0, ey0);
        d_ep[(size_t)(e0 + 1) * 32 + lane] = __floats2half2_rn(ex1, ey1);
    }
}

// ---------------- node projections (layer 0), fp16 outputs ----------------
__global__ void node_proj_k(const float* __restrict__ x,
                            const float* __restrict__ Wl, const float* __restrict__ bl,
                            const float* __restrict__ Wr, const float* __restrict__ br) {
    __shared__ float sWl[64 * 64];
    __shared__ float sWr[64 * 64];
    __shared__ float sx[16 * 64];
    for (int i = threadIdx.x; i < 64 * 16; i += blockDim.x) {
        reinterpret_cast<float4*>(sWl)[i] = reinterpret_cast<const float4*>(Wl)[i];
        reinterpret_cast<float4*>(sWr)[i] = reinterpret_cast<const float4*>(Wr)[i];
    }
    int c  = threadIdx.x & 63;
    int rl = threadIdx.x >> 6;
    float blc = bl[c], brc = br[c];
    for (int base = blockIdx.x * 16; base < NN; base += gridDim.x * 16) {
        __syncthreads();
        for (int i = threadIdx.x; i < 16 * 16; i += 256) {
            int r = base + (i >> 4);
            reinterpret_cast<float4*>(sx)[i] = (r < NN)
                ? reinterpret_cast<const float4*>(x)[(size_t)r * 16 + (i & 15)]
                : make_float4(0.f, 0.f, 0.f, 0.f);
        }
        __syncthreads();
        float s0 = blc, s1 = blc, s2 = blc, s3 = blc;
        float t0 = brc, t1 = brc, t2 = brc, t3 = brc;
        const float* xrow = sx + rl * 4 * 64;
#pragma unroll
        for (int k = 0; k < 64; k++) {
            float wl = sWl[k * 64 + c];
            float wr = sWr[k * 64 + c];
            float x0 = xrow[0 * 64 + k];
            float x1 = xrow[1 * 64 + k];
            float x2 = xrow[2 * 64 + k];
            float x3 = xrow[3 * 64 + k];
            s0 += x0 * wl; t0 += x0 * wr;
            s1 += x1 * wl; t1 += x1 * wr;
            s2 += x2 * wl; t2 += x2 * wr;
            s3 += x3 * wl; t3 += x3 * wr;
        }
        int r0 = base + rl * 4;
        if (r0 + 0 < NN) { d_xl[(size_t)(r0 + 0) * 64 + c] = __float2half(s0); d_xr[(size_t)(r0 + 0) * 64 + c] = __float2half(t0); }
        if (r0 + 1 < NN) { d_xl[(size_t)(r0 + 1) * 64 + c] = __float2half(s1); d_xr[(size_t)(r0 + 1) * 64 + c] = __float2half(t1); }
        if (r0 + 2 < NN) { d_xl[(size_t)(r0 + 2) * 64 + c] = __float2half(s2); d_xr[(size_t)(r0 + 2) * 64 + c] = __float2half(t2); }
        if (r0 + 3 < NN) { d_xl[(size_t)(r0 + 3) * 64 + c] = __float2half(s3); d_xr[(size_t)(r0 + 3) * 64 + c] = __float2half(t3); }
    }
}

// ---------------- node projection (layer 1): fuses layer-0 finalize ----------------
__global__ void node_proj_fused_k(const float* __restrict__ bias0,
                                  const float* __restrict__ Wl, const float* __restrict__ bl,
                                  const float* __restrict__ Wr, const float* __restrict__ br) {
    __shared__ float sWl[64 * 64];
    __shared__ float sWr[64 * 64];
    __shared__ float sx[16 * 64];
    for (int i = threadIdx.x; i < 64 * 16; i += blockDim.x) {
        reinterpret_cast<float4*>(sWl)[i] = reinterpret_cast<const float4*>(Wl)[i];
        reinterpret_cast<float4*>(sWr)[i] = reinterpret_cast<const float4*>(Wr)[i];
    }
    int c  = threadIdx.x & 63;
    int rl = threadIdx.x >> 6;
    float blc = bl[c], brc = br[c];
    for (int base = blockIdx.x * 16; base < NN; base += gridDim.x * 16) {
        __syncthreads();
        for (int i = threadIdx.x; i < 16 * 16; i += 256) {
            int r = base + (i >> 4);
            int part = i & 15;
            float4 v = make_float4(0.f, 0.f, 0.f, 0.f);
            if (r < NN) {
                float inv = 1.0f / d_den[r * 4 + (part >> 2)];
                float4 a = reinterpret_cast<const float4*>(d_acc)[(size_t)r * 16 + part];
                float4 b = reinterpret_cast<const float4*>(bias0)[part];
                v.x = fmaxf(a.x * inv + b.x, 0.0f);
                v.y = fmaxf(a.y * inv + b.y, 0.0f);
                v.z = fmaxf(a.z * inv + b.z, 0.0f);
                v.w = fmaxf(a.w * inv + b.w, 0.0f);
            }
            reinterpret_cast<float4*>(sx)[i] = v;
        }
        __syncthreads();
        float s0 = blc, s1 = blc, s2 = blc, s3 = blc;
        float t0 = brc, t1 = brc, t2 = brc, t3 = brc;
        const float* xrow = sx + rl * 4 * 64;
#pragma unroll
        for (int k = 0; k < 64; k++) {
            float wl = sWl[k * 64 + c];
            float wr = sWr[k * 64 + c];
            float x0 = xrow[0 * 64 + k];
            float x1 = xrow[1 * 64 + k];
            float x2 = xrow[2 * 64 + k];
            float x3 = xrow[3 * 64 + k];
            s0 += x0 * wl; t0 += x0 * wr;
            s1 += x1 * wl; t1 += x1 * wr;
            s2 += x2 * wl; t2 += x2 * wr;
            s3 += x3 * wl; t3 += x3 * wr;
        }
        int r0 = base + rl * 4;
        if (r0 + 0 < NN) { d_xl[(size_t)(r0 + 0) * 64 + c] = __float2half(s0); d_xr[(size_t)(r0 + 0) * 64 + c] = __float2half(t0); }
        if (r0 + 1 < NN) { d_xl[(size_t)(r0 + 1) * 64 + c] = __float2half(s1); d_xr[(size_t)(r0 + 1) * 64 + c] = __float2half(t1); }
        if (r0 + 2 < NN) { d_xl[(size_t)(r0 + 2) * 64 + c] = __float2half(s2); d_xr[(size_t)(r0 + 2) * 64 + c] = __float2half(t2); }
        if (r0 + 3 < NN) { d_xl[(size_t)(r0 + 3) * 64 + c] = __float2half(s3); d_xr[(size_t)(r0 + 3) * 64 + c] = __float2half(t3); }
    }
}

// ---------------- edge pass: 4 edges per warp iteration ----------------
// Quad (4i..4i+3); lane l owns channels {2l,2l+1}; head = lane>>3.
// 13 loads in flight per warp iteration -> 2x MLP vs pair version.
// EE and NN divisible by 4 -> quads never straddle the self-loop boundary.
__global__ __launch_bounds__(256)
void edge_pass_k(const int* __restrict__ ei, const float* __restrict__ att) {
    const unsigned F = 0xffffffffu;
    int lane = threadIdx.x & 31;
    float2 at = reinterpret_cast<const float2*>(att)[lane];

    int wid = (blockIdx.x * blockDim.x + threadIdx.x) >> 5;
    int nwarp = (gridDim.x * blockDim.x) >> 5;
    const __half2* xl2p = reinterpret_cast<const __half2*>(d_xl);
    const __half2* xr2p = reinterpret_cast<const __half2*>(d_xr);

    for (int i = wid; i < E2 / 4; i += nwarp) {
        int e0 = 4 * i;
        int4 sq, dq;
        if (e0 < EE) {
            sq = *reinterpret_cast<const int4*>(ei + e0);
            dq = *reinterpret_cast<const int4*>(ei + EE + e0);
        } else {
            int n = e0 - EE;
            sq = make_int4(n, n + 1, n + 2, n + 3);
            dq = sq;
        }
        float2 ep0 = __half22float2(d_ep[(size_t)(e0 + 0) * 32 + lane]);
        float2 ep1 = __half22float2(d_ep[(size_t)(e0 + 1) * 32 + lane]);
        float2 ep2 = __half22float2(d_ep[(size_t)(e0 + 2) * 32 + lane]);
        float2 ep3 = __half22float2(d_ep[(size_t)(e0 + 3) * 32 + lane]);
        float2 xl0 = __half22float2(xl2p[(size_t)sq.x * 32 + lane]);
        float2 xl1 = __half22float2(xl2p[(size_t)sq.y * 32 + lane]);
        float2 xl2 = __half22float2(xl2p[(size_t)sq.z * 32 + lane]);
        float2 xl3 = __half22float2(xl2p[(size_t)sq.w * 32 + lane]);
        float2 xr0 = __half22float2(xr2p[(size_t)dq.x * 32 + lane]);
        float2 xr1 = __half22float2(xr2p[(size_t)dq.y * 32 + lane]);
        float2 xr2 = __half22float2(xr2p[(size_t)dq.z * 32 + lane]);
        float2 xr3 = __half22float2(xr2p[(size_t)dq.w * 32 + lane]);

        float m0x = xl0.x + xr0.x + ep0.x, m0y = xl0.y + xr0.y + ep0.y;
        float m1x = xl1.x + xr1.x + ep1.x, m1y = xl1.y + xr1.y + ep1.y;
        float m2x = xl2.x + xr2.x + ep2.x, m2y = xl2.y + xr2.y + ep2.y;
        float m3x = xl3.x + xr3.x + ep3.x, m3y = xl3.y + xr3.y + ep3.y;
        m0x = (m0x > 0.f) ? m0x : 0.2f * m0x;  m0y = (m0y > 0.f) ? m0y : 0.2f * m0y;
        m1x = (m1x > 0.f) ? m1x : 0.2f * m1x;  m1y = (m1y > 0.f) ? m1y : 0.2f * m1y;
        m2x = (m2x > 0.f) ? m2x : 0.2f * m2x;  m2y = (m2y > 0.f) ? m2y : 0.2f * m2y;
        m3x = (m3x > 0.f) ? m3x : 0.2f * m3x;  m3y = (m3y > 0.f) ? m3y : 0.2f * m3y;
        float s0 = m0x * at.x + m0y * at.y;
        float s1 = m1x * at.x + m1y * at.y;
        float s2 = m2x * at.x + m2y * at.y;
        float s3 = m3x * at.x + m3y * at.y;
        s0 += __shfl_xor_sync(F, s0, 1); s1 += __shfl_xor_sync(F, s1, 1);
        s2 += __shfl_xor_sync(F, s2, 1); s3 += __shfl_xor_sync(F, s3, 1);
        s0 += __shfl_xor_sync(F, s0, 2); s1 += __shfl_xor_sync(F, s1, 2);
        s2 += __shfl_xor_sync(F, s2, 2); s3 += __shfl_xor_sync(F, s3, 2);
        s0 += __shfl_xor_sync(F, s0, 4); s1 += __shfl_xor_sync(F, s1, 4);
        s2 += __shfl_xor_sync(F, s2, 4); s3 += __shfl_xor_sync(F, s3, 4);
        float z0 = __expf(s0);   // softmax without max-shift (scores O(1))
        float z1 = __expf(s1);
        float z2 = __expf(s2);
        float z3 = __expf(s3);

        red2(d_acc + (size_t)dq.x * 64 + 2 * lane, z0 * xl0.x, z0 * xl0.y);
        red2(d_acc + (size_t)dq.y * 64 + 2 * lane, z1 * xl1.x, z1 * xl1.y);
        red2(d_acc + (size_t)dq.z * 64 + 2 * lane, z2 * xl2.x, z2 * xl2.y);
        red2(d_acc + (size_t)dq.w * 64 + 2 * lane, z3 * xl3.x, z3 * xl3.y);
        if ((lane & 7) == 0) {
            int h = lane >> 3;
            atomicAdd(&d_den[(size_t)dq.x * 4 + h], z0);
            atomicAdd(&d_den[(size_t)dq.y * 4 + h], z1);
            atomicAdd(&d_den[(size_t)dq.z * 4 + h], z2);
            atomicAdd(&d_den[(size_t)dq.w * 4 + h], z3);
        }
    }
}

// ---------------- finalize layer 1 fused with global mean pool ----------------
__global__ void node_out_pool_k(const float* __restrict__ bias, const int* __restrict__ batch) {
    int t = blockIdx.x * blockDim.x + threadIdx.x;
    if (t >= NN * 16) return;
    int node = t >> 4;
    int part = t & 15;
    float inv = 1.0f / d_den[node * 4 + (part >> 2)];
    float4 a = reinterpret_cast<const float4*>(d_acc)[t];
    float4 b = reinterpret_cast<const float4*>(bias)[part];
    float vx = fmaxf(a.x * inv + b.x, 0.0f);
    float vy = fmaxf(a.y * inv + b.y, 0.0f);
    float vz = fmaxf(a.z * inv + b.z, 0.0f);
    float vw = fmaxf(a.w * inv + b.w, 0.0f);
    int g = batch[node];
    red4(d_g + g * 64 + part * 4, vx, vy, vz, vw);
    if (part == 0) atomicAdd(&d_gc[g], 1.0f);
}

// ---------------- MLP head ----------------
__global__ void mlp_k(const float* __restrict__ W1, const float* __restrict__ b1,
                      const float* __restrict__ W2, const float* __restrict__ b2,
                      float* __restrict__ out) {
    __shared__ float gx[64];
    __shared__ float hh[128];
    int g = blockIdx.x;
    int t = threadIdx.x;
    if (t < 64) gx[t] = d_g[g * 64 + t] / fmaxf(d_gc[g], 1.0f);
    __syncthreads();
    float s = b1[t];
#pragma unroll
    for (int k = 0; k < 64; k++) s += gx[k] * W1[k * 128 + t];
    hh[t] = fmaxf(s, 0.0f);
    __syncthreads();
    float o = b2[t];
#pragma unroll
    for (int k = 0; k < 128; k++) o += hh[k] * W2[k * 128 + t];
    out[g * 128 + t] = o;
}

// ---------------- launch (single stream, no events) ----------------
extern "C" void kernel_launch(void* const* d_in, const int* in_sizes, int n_in,
                              void* d_out, int out_size) {
    const float* x0     = (const float*)d_in[0];
    const int*   ei     = (const int*)d_in[1];
    const float* ea     = (const float*)d_in[2];
    const int*   batch  = (const int*)d_in[3];
    const float* l0Wl   = (const float*)d_in[4];
    const float* l0bl   = (const float*)d_in[5];
    const float* l0Wr   = (const float*)d_in[6];
    const float* l0br   = (const float*)d_in[7];
    const float* l0We   = (const float*)d_in[8];
    const float* l0att  = (const float*)d_in[9];
    const float* l0bias = (const float*)d_in[10];
    const float* l1Wl   = (const float*)d_in[11];
    const float* l1bl   = (const float*)d_in[12];
    const float* l1Wr   = (const float*)d_in[13];
    const float* l1br   = (const float*)d_in[14];
    const float* l1We   = (const float*)d_in[15];
    const float* l1att  = (const float*)d_in[16];
    const float* l1bias = (const float*)d_in[17];
    const float* W1     = (const float*)d_in[18];
    const float* b1     = (const float*)d_in[19];
    const float* W2     = (const float*)d_in[20];
    const float* b2     = (const float*)d_in[21];
    float* out = (float*)d_out;

    void *pcnt, *ploop, *pacc, *pden, *pg, *pgc;
    cudaGetSymbolAddress(&pcnt, d_cnt);
    cudaGetSymbolAddress(&ploop, d_loop);
    cudaGetSymbolAddress(&pacc, d_acc);
    cudaGetSymbolAddress(&pden, d_den);
    cudaGetSymbolAddress(&pg, d_g);
    cudaGetSymbolAddress(&pgc, d_gc);

    cudaMemsetAsync(pcnt, 0, NN * sizeof(float));
    cudaMemsetAsync(ploop, 0, NN * EDIM * sizeof(float));
    cudaMemsetAsync(pg, 0, GG * HID * sizeof(float));
    cudaMemsetAsync(pgc, 0, GG * sizeof(float));

    loop_accum_k<<<(EE + 255) / 256, 256>>>(ei, ea);

    // ---- layer 0 ----
    ep_k<<<2048, 256>>>(ea, l0We);
    node_proj_k<<<2048, 256>>>(x0, l0Wl, l0bl, l0Wr, l0br);
    cudaMemsetAsync(pacc, 0, (size_t)NN * HID * sizeof(float));
    cudaMemsetAsync(pden, 0, (size_t)NN * 4 * sizeof(float));
    edge_pass_k<<<2048, 256>>>(ei, l0att);

    // ---- layer 1 (layer-0 finalize fused into projection) ----
    ep_k<<<2048, 256>>>(ea, l1We);
    node_proj_fused_k<<<2048, 256>>>(l0bias, l1Wl, l1bl, l1Wr, l1br);
    cudaMemsetAsync(pacc, 0, (size_t)NN * HID * sizeof(float));
    cudaMemsetAsync(pden, 0, (size_t)NN * 4 * sizeof(float));
    edge_pass_k<<<2048, 256>>>(ei, l1att);
    node_out_pool_k<<<(NN * 16 + 255) / 256, 256>>>(l1bias, batch);

    // ---- MLP ----
    mlp_k<<<GG, OUTD>>>(W1, b1, W2, b2, out);
}

// round 13
// speedup vs baseline: 5.7453x; 1.0270x over previous
#include <cuda_runtime.h>
#include <cuda_fp16.h>

#define NN 100000
#define EE 1600000
#define E2 (EE + NN)
#define GG 64
#define HID 64
#define EDIM 16
#define OUTD 128

// ---------------- scratch (device globals; no allocation) ----------------
__device__ float d_cnt[NN];
__device__ float d_loop[NN * EDIM];
__device__ __half d_xl[NN * HID];
__device__ __half d_xr[NN * HID];
__device__ float d_acc[NN * HID];
__device__ float d_den[NN * 4];
__device__ float d_g[GG * HID];
__device__ float d_gc[GG];
__device__ __half2 d_ep0[(size_t)E2 * 32];   // layer-0 ea @ We (fp16 storage)
__device__ __half2 d_ep1[(size_t)E2 * 32];   // layer-1 ea @ We (fp16 storage)

__device__ __forceinline__ void red4(float* p, float a, float b, float c, float d) {
    asm volatile("red.global.add.v4.f32 [%0], {%1,%2,%3,%4};"
                 :: "l"(p), "f"(a), "f"(b), "f"(c), "f"(d) : "memory");
}
__device__ __forceinline__ void red2(float* p, float a, float b) {
    asm volatile("red.global.add.v2.f32 [%0], {%1,%2};"
                 :: "l"(p), "f"(a), "f"(b) : "memory");
}

// ---------------- self-loop mean edge attr (sum; division folded into ep_both_k) ----------------
__global__ void loop_accum_k(const int* __restrict__ ei, const float* __restrict__ ea) {
    int e = blockIdx.x * blockDim.x + threadIdx.x;
    if (e >= EE) return;
    int dst = ei[EE + e];
    const float4* a4 = reinterpret_cast<const float4*>(ea + (size_t)e * EDIM);
    float* o = d_loop + (size_t)dst * EDIM;
#pragma unroll
    for (int i = 0; i < 4; i++) {
        float4 v = a4[i];
        red4(o + 4 * i, v.x, v.y, v.z, v.w);
    }
    atomicAdd(&d_cnt[dst], 1.0f);
}

// ---------------- edge projections for BOTH layers in one pass ----------------
// Warp handles an edge pair; the 32 shuffle broadcasts of ea are SHARED between
// layers. MACs in fp32 (fp16 only as storage format). Self-loop attrs
// normalized by cnt inline. Writes device globals directly.
__global__ __launch_bounds__(256)
void ep_both_k(const float* __restrict__ ea,
               const float* __restrict__ We0, const float* __restrict__ We1) {
    const unsigned F = 0xffffffffu;
    int lane = threadIdx.x & 31;
    float2 w0[EDIM], w1[EDIM];
    const float2* We0p = reinterpret_cast<const float2*>(We0);
    const float2* We1p = reinterpret_cast<const float2*>(We1);
#pragma unroll
    for (int k = 0; k < EDIM; k++) {
        w0[k] = We0p[k * 32 + lane];
        w1[k] = We1p[k * 32 + lane];
    }

    int wid = (blockIdx.x * blockDim.x + threadIdx.x) >> 5;
    int nwarp = (gridDim.x * blockDim.x) >> 5;

    for (int i = wid; i < E2 / 2; i += nwarp) {
        int e0 = 2 * i;
        float av;
        if (e0 < EE) {
            av = ea[(size_t)e0 * EDIM + lane];
        } else {
            int n0 = e0 - EE;
            int n = n0 + (lane >> 4);
            av = d_loop[(size_t)n0 * EDIM + lane] / fmaxf(d_cnt[n], 1.0f);
        }
        float x00 = 0.f, y00 = 0.f, x01 = 0.f, y01 = 0.f;   // edge0: layer0, layer1
        float x10 = 0.f, y10 = 0.f, x11 = 0.f, y11 = 0.f;   // edge1: layer0, layer1
#pragma unroll
        for (int k = 0; k < EDIM; k++) {
            float a0 = __shfl_sync(F, av, k);
            float a1 = __shfl_sync(F, av, k + 16);
            x00 += a0 * w0[k].x;  y00 += a0 * w0[k].y;
            x01 += a0 * w1[k].x;  y01 += a0 * w1[k].y;
            x10 += a1 * w0[k].x;  y10 += a1 * w0[k].y;
            x11 += a1 * w1[k].x;  y11 += a1 * w1[k].y;
        }
        d_ep0[(size_t)e0 * 32 + lane]       = __floats2half2_rn(x00, y00);
        d_ep0[(size_t)(e0 + 1) * 32 + lane] = __floats2half2_rn(x10, y10);
        d_ep1[(size_t)e0 * 32 + lane]       = __floats2half2_rn(x01, y01);
        d_ep1[(size_t)(e0 + 1) * 32 + lane] = __floats2half2_rn(x11, y11);
    }
}

// ---------------- node projections (layer 0), fp16 outputs ----------------
__global__ void node_proj_k(const float* __restrict__ x,
                            const float* __restrict__ Wl, const float* __restrict__ bl,
                            const float* __restrict__ Wr, const float* __restrict__ br) {
    __shared__ float sWl[64 * 64];
    __shared__ float sWr[64 * 64];
    __shared__ float sx[16 * 64];
    for (int i = threadIdx.x; i < 64 * 16; i += blockDim.x) {
        reinterpret_cast<float4*>(sWl)[i] = reinterpret_cast<const float4*>(Wl)[i];
        reinterpret_cast<float4*>(sWr)[i] = reinterpret_cast<const float4*>(Wr)[i];
    }
    int c  = threadIdx.x & 63;
    int rl = threadIdx.x >> 6;
    float blc = bl[c], brc = br[c];
    for (int base = blockIdx.x * 16; base < NN; base += gridDim.x * 16) {
        __syncthreads();
        for (int i = threadIdx.x; i < 16 * 16; i += 256) {
            int r = base + (i >> 4);
            reinterpret_cast<float4*>(sx)[i] = (r < NN)
                ? reinterpret_cast<const float4*>(x)[(size_t)r * 16 + (i & 15)]
                : make_float4(0.f, 0.f, 0.f, 0.f);
        }
        __syncthreads();
        float s0 = blc, s1 = blc, s2 = blc, s3 = blc;
        float t0 = brc, t1 = brc, t2 = brc, t3 = brc;
        const float* xrow = sx + rl * 4 * 64;
#pragma unroll
        for (int k = 0; k < 64; k++) {
            float wl = sWl[k * 64 + c];
            float wr = sWr[k * 64 + c];
            float x0 = xrow[0 * 64 + k];
            float x1 = xrow[1 * 64 + k];
            float x2 = xrow[2 * 64 + k];
            float x3 = xrow[3 * 64 + k];
            s0 += x0 * wl; t0 += x0 * wr;
            s1 += x1 * wl; t1 += x1 * wr;
            s2 += x2 * wl; t2 += x2 * wr;
            s3 += x3 * wl; t3 += x3 * wr;
        }
        int r0 = base + rl * 4;
        if (r0 + 0 < NN) { d_xl[(size_t)(r0 + 0) * 64 + c] = __float2half(s0); d_xr[(size_t)(r0 + 0) * 64 + c] = __float2half(t0); }
        if (r0 + 1 < NN) { d_xl[(size_t)(r0 + 1) * 64 + c] = __float2half(s1); d_xr[(size_t)(r0 + 1) * 64 + c] = __float2half(t1); }
        if (r0 + 2 < NN) { d_xl[(size_t)(r0 + 2) * 64 + c] = __float2half(s2); d_xr[(size_t)(r0 + 2) * 64 + c] = __float2half(t2); }
        if (r0 + 3 < NN) { d_xl[(size_t)(r0 + 3) * 64 + c] = __float2half(s3); d_xr[(size_t)(r0 + 3) * 64 + c] = __float2half(t3); }
    }
}

// ---------------- node projection (layer 1): fuses layer-0 finalize ----------------
__global__ void node_proj_fused_k(const float* __restrict__ bias0,
                                  const float* __restrict__ Wl, const float* __restrict__ bl,
                                  const float* __restrict__ Wr, const float* __restrict__ br) {
    __shared__ float sWl[64 * 64];
    __shared__ float sWr[64 * 64];
    __shared__ float sx[16 * 64];
    for (int i = threadIdx.x; i < 64 * 16; i += blockDim.x) {
        reinterpret_cast<float4*>(sWl)[i] = reinterpret_cast<const float4*>(Wl)[i];
        reinterpret_cast<float4*>(sWr)[i] = reinterpret_cast<const float4*>(Wr)[i];
    }
    int c  = threadIdx.x & 63;
    int rl = threadIdx.x >> 6;
    float blc = bl[c], brc = br[c];
    for (int base = blockIdx.x * 16; base < NN; base += gridDim.x * 16) {
        __syncthreads();
        for (int i = threadIdx.x; i < 16 * 16; i += 256) {
            int r = base + (i >> 4);
            int part = i & 15;
            float4 v = make_float4(0.f, 0.f, 0.f, 0.f);
            if (r < NN) {
                float inv = 1.0f / d_den[r * 4 + (part >> 2)];
                float4 a = reinterpret_cast<const float4*>(d_acc)[(size_t)r * 16 + part];
                float4 b = reinterpret_cast<const float4*>(bias0)[part];
                v.x = fmaxf(a.x * inv + b.x, 0.0f);
                v.y = fmaxf(a.y * inv + b.y, 0.0f);
                v.z = fmaxf(a.z * inv + b.z, 0.0f);
                v.w = fmaxf(a.w * inv + b.w, 0.0f);
            }
            reinterpret_cast<float4*>(sx)[i] = v;
        }
        __syncthreads();
        float s0 = blc, s1 = blc, s2 = blc, s3 = blc;
        float t0 = brc, t1 = brc, t2 = brc, t3 = brc;
        const float* xrow = sx + rl * 4 * 64;
#pragma unroll
        for (int k = 0; k < 64; k++) {
            float wl = sWl[k * 64 + c];
            float wr = sWr[k * 64 + c];
            float x0 = xrow[0 * 64 + k];
            float x1 = xrow[1 * 64 + k];
            float x2 = xrow[2 * 64 + k];
            float x3 = xrow[3 * 64 + k];
            s0 += x0 * wl; t0 += x0 * wr;
            s1 += x1 * wl; t1 += x1 * wr;
            s2 += x2 * wl; t2 += x2 * wr;
            s3 += x3 * wl; t3 += x3 * wr;
        }
        int r0 = base + rl * 4;
        if (r0 + 0 < NN) { d_xl[(size_t)(r0 + 0) * 64 + c] = __float2half(s0); d_xr[(size_t)(r0 + 0) * 64 + c] = __float2half(t0); }
        if (r0 + 1 < NN) { d_xl[(size_t)(r0 + 1) * 64 + c] = __float2half(s1); d_xr[(size_t)(r0 + 1) * 64 + c] = __float2half(t1); }
        if (r0 + 2 < NN) { d_xl[(size_t)(r0 + 2) * 64 + c] = __float2half(s2); d_xr[(size_t)(r0 + 2) * 64 + c] = __float2half(t2); }
        if (r0 + 3 < NN) { d_xl[(size_t)(r0 + 3) * 64 + c] = __float2half(s3); d_xr[(size_t)(r0 + 3) * 64 + c] = __float2half(t3); }
    }
}

// ---------------- edge pass: 4 edges per warp iteration ----------------
// ep pointer is a REAL device pointer (cudaGetSymbolAddress) — never the
// host-side shadow of a __device__ symbol (GB300 ATS silently reads host
// memory instead of faulting).
__global__ __launch_bounds__(256)
void edge_pass_k(const int* __restrict__ ei, const float* __restrict__ att,
                 const __half2* __restrict__ ep) {
    const unsigned F = 0xffffffffu;
    int lane = threadIdx.x & 31;
    float2 at = reinterpret_cast<const float2*>(att)[lane];

    int wid = (blockIdx.x * blockDim.x + threadIdx.x) >> 5;
    int nwarp = (gridDim.x * blockDim.x) >> 5;
    const __half2* xl2p = reinterpret_cast<const __half2*>(d_xl);
    const __half2* xr2p = reinterpret_cast<const __half2*>(d_xr);

    for (int i = wid; i < E2 / 4; i += nwarp) {
        int e0 = 4 * i;
        int4 sq, dq;
        if (e0 < EE) {
            sq = *reinterpret_cast<const int4*>(ei + e0);
            dq = *reinterpret_cast<const int4*>(ei + EE + e0);
        } else {
            int n = e0 - EE;
            sq = make_int4(n, n + 1, n + 2, n + 3);
            dq = sq;
        }
        float2 ep0 = __half22float2(ep[(size_t)(e0 + 0) * 32 + lane]);
        float2 ep1 = __half22float2(ep[(size_t)(e0 + 1) * 32 + lane]);
        float2 ep2 = __half22float2(ep[(size_t)(e0 + 2) * 32 + lane]);
        float2 ep3 = __half22float2(ep[(size_t)(e0 + 3) * 32 + lane]);
        float2 xl0 = __half22float2(xl2p[(size_t)sq.x * 32 + lane]);
        float2 xl1 = __half22float2(xl2p[(size_t)sq.y * 32 + lane]);
        float2 xl2 = __half22float2(xl2p[(size_t)sq.z * 32 + lane]);
        float2 xl3 = __half22float2(xl2p[(size_t)sq.w * 32 + lane]);
        float2 xr0 = __half22float2(xr2p[(size_t)dq.x * 32 + lane]);
        float2 xr1 = __half22float2(xr2p[(size_t)dq.y * 32 + lane]);
        float2 xr2 = __half22float2(xr2p[(size_t)dq.z * 32 + lane]);
        float2 xr3 = __half22float2(xr2p[(size_t)dq.w * 32 + lane]);

        float m0x = xl0.x + xr0.x + ep0.x, m0y = xl0.y + xr0.y + ep0.y;
        float m1x = xl1.x + xr1.x + ep1.x, m1y = xl1.y + xr1.y + ep1.y;
        float m2x = xl2.x + xr2.x + ep2.x, m2y = xl2.y + xr2.y + ep2.y;
        float m3x = xl3.x + xr3.x + ep3.x, m3y = xl3.y + xr3.y + ep3.y;
        m0x = (m0x > 0.f) ? m0x : 0.2f * m0x;  m0y = (m0y > 0.f) ? m0y : 0.2f * m0y;
        m1x = (m1x > 0.f) ? m1x : 0.2f * m1x;  m1y = (m1y > 0.f) ? m1y : 0.2f * m1y;
        m2x = (m2x > 0.f) ? m2x : 0.2f * m2x;  m2y = (m2y > 0.f) ? m2y : 0.2f * m2y;
        m3x = (m3x > 0.f) ? m3x : 0.2f * m3x;  m3y = (m3y > 0.f) ? m3y : 0.2f * m3y;
        float s0 = m0x * at.x + m0y * at.y;
        float s1 = m1x * at.x + m1y * at.y;
        float s2 = m2x * at.x + m2y * at.y;
        float s3 = m3x * at.x + m3y * at.y;
        s0 += __shfl_xor_sync(F, s0, 1); s1 += __shfl_xor_sync(F, s1, 1);
        s2 += __shfl_xor_sync(F, s2, 1); s3 += __shfl_xor_sync(F, s3, 1);
        s0 += __shfl_xor_sync(F, s0, 2); s1 += __shfl_xor_sync(F, s1, 2);
        s2 += __shfl_xor_sync(F, s2, 2); s3 += __shfl_xor_sync(F, s3, 2);
        s0 += __shfl_xor_sync(F, s0, 4); s1 += __shfl_xor_sync(F, s1, 4);
        s2 += __shfl_xor_sync(F, s2, 4); s3 += __shfl_xor_sync(F, s3, 4);
        float z0 = __expf(s0);   // softmax without max-shift (scores O(1))
        float z1 = __expf(s1);
        float z2 = __expf(s2);
        float z3 = __expf(s3);

        red2(d_acc + (size_t)dq.x * 64 + 2 * lane, z0 * xl0.x, z0 * xl0.y);
        red2(d_acc + (size_t)dq.y * 64 + 2 * lane, z1 * xl1.x, z1 * xl1.y);
        red2(d_acc + (size_t)dq.z * 64 + 2 * lane, z2 * xl2.x, z2 * xl2.y);
        red2(d_acc + (size_t)dq.w * 64 + 2 * lane, z3 * xl3.x, z3 * xl3.y);
        if ((lane & 7) == 0) {
            int h = lane >> 3;
            atomicAdd(&d_den[(size_t)dq.x * 4 + h], z0);
            atomicAdd(&d_den[(size_t)dq.y * 4 + h], z1);
            atomicAdd(&d_den[(size_t)dq.z * 4 + h], z2);
            atomicAdd(&d_den[(size_t)dq.w * 4 + h], z3);
        }
    }
}

// ---------------- finalize layer 1 fused with global mean pool ----------------
__global__ void node_out_pool_k(const float* __restrict__ bias, const int* __restrict__ batch) {
    int t = blockIdx.x * blockDim.x + threadIdx.x;
    if (t >= NN * 16) return;
    int node = t >> 4;
    int part = t & 15;
    float inv = 1.0f / d_den[node * 4 + (part >> 2)];
    float4 a = reinterpret_cast<const float4*>(d_acc)[t];
    float4 b = reinterpret_cast<const float4*>(bias)[part];
    float vx = fmaxf(a.x * inv + b.x, 0.0f);
    float vy = fmaxf(a.y * inv + b.y, 0.0f);
    float vz = fmaxf(a.z * inv + b.z, 0.0f);
    float vw = fmaxf(a.w * inv + b.w, 0.0f);
    int g = batch[node];
    red4(d_g + g * 64 + part * 4, vx, vy, vz, vw);
    if (part == 0) atomicAdd(&d_gc[g], 1.0f);
}

// ---------------- MLP head ----------------
__global__ void mlp_k(const float* __restrict__ W1, const float* __restrict__ b1,
                      const float* __restrict__ W2, const float* __restrict__ b2,
                      float* __restrict__ out) {
    __shared__ float gx[64];
    __shared__ float hh[128];
    int g = blockIdx.x;
    int t = threadIdx.x;
    if (t < 64) gx[t] = d_g[g * 64 + t] / fmaxf(d_gc[g], 1.0f);
    __syncthreads();
    float s = b1[t];
#pragma unroll
    for (int k = 0; k < 64; k++) s += gx[k] * W1[k * 128 + t];
    hh[t] = fmaxf(s, 0.0f);
    __syncthreads();
    float o = b2[t];
#pragma unroll
    for (int k = 0; k < 128; k++) o += hh[k] * W2[k * 128 + t];
    out[g * 128 + t] = o;
}

// ---------------- launch (single stream) ----------------
extern "C" void kernel_launch(void* const* d_in, const int* in_sizes, int n_in,
                              void* d_out, int out_size) {
    const float* x0     = (const float*)d_in[0];
    const int*   ei     = (const int*)d_in[1];
    const float* ea     = (const float*)d_in[2];
    const int*   batch  = (const int*)d_in[3];
    const float* l0Wl   = (const float*)d_in[4];
    const float* l0bl   = (const float*)d_in[5];
    const float* l0Wr   = (const float*)d_in[6];
    const float* l0br   = (const float*)d_in[7];
    const float* l0We   = (const float*)d_in[8];
    const float* l0att  = (const float*)d_in[9];
    const float* l0bias = (const float*)d_in[10];
    const float* l1Wl   = (const float*)d_in[11];
    const float* l1bl   = (const float*)d_in[12];
    const float* l1Wr   = (const float*)d_in[13];
    const float* l1br   = (const float*)d_in[14];
    const float* l1We   = (const float*)d_in[15];
    const float* l1att  = (const float*)d_in[16];
    const float* l1bias = (const float*)d_in[17];
    const float* W1     = (const float*)d_in[18];
    const float* b1     = (const float*)d_in[19];
    const float* W2     = (const float*)d_in[20];
    const float* b2     = (const float*)d_in[21];
    float* out = (float*)d_out;

    void *pcnt, *ploop, *pacc, *pden, *pg, *pgc, *pep0, *pep1;
    cudaGetSymbolAddress(&pcnt, d_cnt);
    cudaGetSymbolAddress(&ploop, d_loop);
    cudaGetSymbolAddress(&pacc, d_acc);
    cudaGetSymbolAddress(&pden, d_den);
    cudaGetSymbolAddress(&pg, d_g);
    cudaGetSymbolAddress(&pgc, d_gc);
    cudaGetSymbolAddress(&pep0, d_ep0);   // REAL device pointers for kernel args
    cudaGetSymbolAddress(&pep1, d_ep1);

    cudaMemsetAsync(pcnt, 0, NN * sizeof(float));
    cudaMemsetAsync(ploop, 0, NN * EDIM * sizeof(float));
    cudaMemsetAsync(pg, 0, GG * HID * sizeof(float));
    cudaMemsetAsync(pgc, 0, GG * sizeof(float));

    loop_accum_k<<<(EE + 255) / 256, 256>>>(ei, ea);

    // both layers' edge projections in one pass (fp32 math, fp16 storage)
    ep_both_k<<<2048, 256>>>(ea, l0We, l1We);

    // ---- layer 0 ----
    node_proj_k<<<2048, 256>>>(x0, l0Wl, l0bl, l0Wr, l0br);
    cudaMemsetAsync(pacc, 0, (size_t)NN * HID * sizeof(float));
    cudaMemsetAsync(pden, 0, (size_t)NN * 4 * sizeof(float));
    edge_pass_k<<<2048, 256>>>(ei, l0att, (const __half2*)pep0);

    // ---- layer 1 (layer-0 finalize fused into projection) ----
    node_proj_fused_k<<<2048, 256>>>(l0bias, l1Wl, l1bl, l1Wr, l1br);
    cudaMemsetAsync(pacc, 0, (size_t)NN * HID * sizeof(float));
    cudaMemsetAsync(pden, 0, (size_t)NN * 4 * sizeof(float));
    edge_pass_k<<<2048, 256>>>(ei, l1att, (const __half2*)pep1);
    node_out_pool_k<<<(NN * 16 + 255) / 256, 256>>>(l1bias, batch);

    // ---- MLP ----
    mlp_k<<<GG, OUTD>>>(W1, b1, W2, b2, out);
}

// round 14
// speedup vs baseline: 6.1768x; 1.0751x over previous
#include <cuda_runtime.h>
#include <cuda_fp16.h>

#define NN 100000
#define EE 1600000
#define E2 (EE + NN)
#define NP (E2 / 2)
#define GG 64
#define HID 64
#define EDIM 16
#define OUTD 128

// ---------------- scratch (device globals; no allocation) ----------------
__device__ float d_cnt[NN];
__device__ float d_loop[NN * EDIM];
__device__ __half d_xl[NN * HID];
__device__ __half d_xr[NN * HID];
__device__ float d_acc[NN * HID];
__device__ float d_den[NN * 4];
__device__ float d_g[GG * HID];
__device__ float d_gc[GG];
// pair-interleaved ep: ep[pair*32+lane] = u64{ half2(edge0 ch2l,2l+1), half2(edge1) }
__device__ unsigned long long d_ep0[(size_t)NP * 32];
__device__ unsigned long long d_ep1[(size_t)NP * 32];

__device__ __forceinline__ void red4(float* p, float a, float b, float c, float d) {
    asm volatile("red.global.add.v4.f32 [%0], {%1,%2,%3,%4};"
                 :: "l"(p), "f"(a), "f"(b), "f"(c), "f"(d) : "memory");
}
__device__ __forceinline__ void red2(float* p, float a, float b) {
    asm volatile("red.global.add.v2.f32 [%0], {%1,%2};"
                 :: "l"(p), "f"(a), "f"(b) : "memory");
}
// packed f32x2 helpers
__device__ __forceinline__ unsigned long long packdup(float a) {
    unsigned long long r;
    asm("mov.b64 %0, {%1, %1};" : "=l"(r) : "f"(a));
    return r;
}
__device__ __forceinline__ void ffma2(unsigned long long& acc, unsigned long long a,
                                      unsigned long long b) {
    asm("fma.rn.f32x2 %0, %1, %2, %3;" : "=l"(acc) : "l"(a), "l"(b), "l"(acc));
}
__device__ __forceinline__ unsigned pack_h2(unsigned long long acc) {
    float x, y;
    asm("mov.b64 {%0, %1}, %2;" : "=f"(x), "=f"(y) : "l"(acc));
    __half2 h = __floats2half2_rn(x, y);
    return *reinterpret_cast<unsigned*>(&h);
}

// ---------------- self-loop mean edge attr (sum; division folded into ep_both_k) ----------------
__global__ void loop_accum_k(const int* __restrict__ ei, const float* __restrict__ ea) {
    int e = blockIdx.x * blockDim.x + threadIdx.x;
    if (e >= EE) return;
    int dst = ei[EE + e];
    const float4* a4 = reinterpret_cast<const float4*>(ea + (size_t)e * EDIM);
    float* o = d_loop + (size_t)dst * EDIM;
#pragma unroll
    for (int i = 0; i < 4; i++) {
        float4 v = a4[i];
        red4(o + 4 * i, v.x, v.y, v.z, v.w);
    }
    atomicAdd(&d_cnt[dst], 1.0f);
}

// ---------------- edge projections for BOTH layers, packed f32x2 math ----------------
// Warp handles an edge pair; 32 shuffle broadcasts shared across layers;
// MACs are FFMA2 (fp32 lanewise, bit-identical rounding to scalar FFMA).
__global__ void ep_both_k(const float* __restrict__ ea,
                          const float* __restrict__ We0, const float* __restrict__ We1) {
    const unsigned F = 0xffffffffu;
    int lane = threadIdx.x & 31;
    unsigned long long w0[EDIM], w1[EDIM];
    const unsigned long long* We0q = reinterpret_cast<const unsigned long long*>(We0);
    const unsigned long long* We1q = reinterpret_cast<const unsigned long long*>(We1);
#pragma unroll
    for (int k = 0; k < EDIM; k++) {
        w0[k] = We0q[k * 32 + lane];   // (We[k][2l], We[k][2l+1]) packed
        w1[k] = We1q[k * 32 + lane];
    }

    int wid = (blockIdx.x * blockDim.x + threadIdx.x) >> 5;
    int nwarp = (gridDim.x * blockDim.x) >> 5;

    for (int i = wid; i < NP; i += nwarp) {
        int e0 = 2 * i;
        float av;
        if (e0 < EE) {
            av = ea[(size_t)e0 * EDIM + lane];
        } else {
            int n0 = e0 - EE;
            int n = n0 + (lane >> 4);
            av = d_loop[(size_t)n0 * EDIM + lane] / fmaxf(d_cnt[n], 1.0f);
        }
        unsigned long long a00 = 0ull, a01 = 0ull, a10 = 0ull, a11 = 0ull;
#pragma unroll
        for (int k = 0; k < EDIM; k++) {
            unsigned long long p0 = packdup(__shfl_sync(F, av, k));
            unsigned long long p1 = packdup(__shfl_sync(F, av, k + 16));
            ffma2(a00, p0, w0[k]);   // edge0, layer0
            ffma2(a01, p0, w1[k]);   // edge0, layer1
            ffma2(a10, p1, w0[k]);   // edge1, layer0
            ffma2(a11, p1, w1[k]);   // edge1, layer1
        }
        unsigned long long v0, v1;
        asm("mov.b64 %0, {%1,%2};" : "=l"(v0) : "r"(pack_h2(a00)), "r"(pack_h2(a10)));
        asm("mov.b64 %0, {%1,%2};" : "=l"(v1) : "r"(pack_h2(a01)), "r"(pack_h2(a11)));
        d_ep0[(size_t)i * 32 + lane] = v0;
        d_ep1[(size_t)i * 32 + lane] = v1;
    }
}

// ---------------- node projections (layer 0), fp16 outputs ----------------
__global__ void node_proj_k(const float* __restrict__ x,
                            const float* __restrict__ Wl, const float* __restrict__ bl,
                            const float* __restrict__ Wr, const float* __restrict__ br) {
    __shared__ float sWl[64 * 64];
    __shared__ float sWr[64 * 64];
    __shared__ float sx[16 * 64];
    for (int i = threadIdx.x; i < 64 * 16; i += blockDim.x) {
        reinterpret_cast<float4*>(sWl)[i] = reinterpret_cast<const float4*>(Wl)[i];
        reinterpret_cast<float4*>(sWr)[i] = reinterpret_cast<const float4*>(Wr)[i];
    }
    int c  = threadIdx.x & 63;
    int rl = threadIdx.x >> 6;
    float blc = bl[c], brc = br[c];
    for (int base = blockIdx.x * 16; base < NN; base += gridDim.x * 16) {
        __syncthreads();
        for (int i = threadIdx.x; i < 16 * 16; i += 256) {
            int r = base + (i >> 4);
            reinterpret_cast<float4*>(sx)[i] = (r < NN)
                ? reinterpret_cast<const float4*>(x)[(size_t)r * 16 + (i & 15)]
                : make_float4(0.f, 0.f, 0.f, 0.f);
        }
        __syncthreads();
        float s0 = blc, s1 = blc, s2 = blc, s3 = blc;
        float t0 = brc, t1 = brc, t2 = brc, t3 = brc;
        const float* xrow = sx + rl * 4 * 64;
#pragma unroll
        for (int k = 0; k < 64; k++) {
            float wl = sWl[k * 64 + c];
            float wr = sWr[k * 64 + c];
            float x0 = xrow[0 * 64 + k];
            float x1 = xrow[1 * 64 + k];
            float x2 = xrow[2 * 64 + k];
            float x3 = xrow[3 * 64 + k];
            s0 += x0 * wl; t0 += x0 * wr;
            s1 += x1 * wl; t1 += x1 * wr;
            s2 += x2 * wl; t2 += x2 * wr;
            s3 += x3 * wl; t3 += x3 * wr;
        }
        int r0 = base + rl * 4;
        if (r0 + 0 < NN) { d_xl[(size_t)(r0 + 0) * 64 + c] = __float2half(s0); d_xr[(size_t)(r0 + 0) * 64 + c] = __float2half(t0); }
        if (r0 + 1 < NN) { d_xl[(size_t)(r0 + 1) * 64 + c] = __float2half(s1); d_xr[(size_t)(r0 + 1) * 64 + c] = __float2half(t1); }
        if (r0 + 2 < NN) { d_xl[(size_t)(r0 + 2) * 64 + c] = __float2half(s2); d_xr[(size_t)(r0 + 2) * 64 + c] = __float2half(t2); }
        if (r0 + 3 < NN) { d_xl[(size_t)(r0 + 3) * 64 + c] = __float2half(s3); d_xr[(size_t)(r0 + 3) * 64 + c] = __float2half(t3); }
    }
}

// ---------------- node projection (layer 1): fuses layer-0 finalize ----------------
__global__ void node_proj_fused_k(const float* __restrict__ bias0,
                                  const float* __restrict__ Wl, const float* __restrict__ bl,
                                  const float* __restrict__ Wr, const float* __restrict__ br) {
    __shared__ float sWl[64 * 64];
    __shared__ float sWr[64 * 64];
    __shared__ float sx[16 * 64];
    for (int i = threadIdx.x; i < 64 * 16; i += blockDim.x) {
        reinterpret_cast<float4*>(sWl)[i] = reinterpret_cast<const float4*>(Wl)[i];
        reinterpret_cast<float4*>(sWr)[i] = reinterpret_cast<const float4*>(Wr)[i];
    }
    int c  = threadIdx.x & 63;
    int rl = threadIdx.x >> 6;
    float blc = bl[c], brc = br[c];
    for (int base = blockIdx.x * 16; base < NN; base += gridDim.x * 16) {
        __syncthreads();
        for (int i = threadIdx.x; i < 16 * 16; i += 256) {
            int r = base + (i >> 4);
            int part = i & 15;
            float4 v = make_float4(0.f, 0.f, 0.f, 0.f);
            if (r < NN) {
                float inv = 1.0f / d_den[r * 4 + (part >> 2)];
                float4 a = reinterpret_cast<const float4*>(d_acc)[(size_t)r * 16 + part];
                float4 b = reinterpret_cast<const float4*>(bias0)[part];
                v.x = fmaxf(a.x * inv + b.x, 0.0f);
                v.y = fmaxf(a.y * inv + b.y, 0.0f);
                v.z = fmaxf(a.z * inv + b.z, 0.0f);
                v.w = fmaxf(a.w * inv + b.w, 0.0f);
            }
            reinterpret_cast<float4*>(sx)[i] = v;
        }
        __syncthreads();
        float s0 = blc, s1 = blc, s2 = blc, s3 = blc;
        float t0 = brc, t1 = brc, t2 = brc, t3 = brc;
        const float* xrow = sx + rl * 4 * 64;
#pragma unroll
        for (int k = 0; k < 64; k++) {
            float wl = sWl[k * 64 + c];
            float wr = sWr[k * 64 + c];
            float x0 = xrow[0 * 64 + k];
            float x1 = xrow[1 * 64 + k];
            float x2 = xrow[2 * 64 + k];
            float x3 = xrow[3 * 64 + k];
            s0 += x0 * wl; t0 += x0 * wr;
            s1 += x1 * wl; t1 += x1 * wr;
            s2 += x2 * wl; t2 += x2 * wr;
            s3 += x3 * wl; t3 += x3 * wr;
        }
        int r0 = base + rl * 4;
        if (r0 + 0 < NN) { d_xl[(size_t)(r0 + 0) * 64 + c] = __float2half(s0); d_xr[(size_t)(r0 + 0) * 64 + c] = __float2half(t0); }
        if (r0 + 1 < NN) { d_xl[(size_t)(r0 + 1) * 64 + c] = __float2half(s1); d_xr[(size_t)(r0 + 1) * 64 + c] = __float2half(t1); }
        if (r0 + 2 < NN) { d_xl[(size_t)(r0 + 2) * 64 + c] = __float2half(s2); d_xr[(size_t)(r0 + 2) * 64 + c] = __float2half(t2); }
        if (r0 + 3 < NN) { d_xl[(size_t)(r0 + 3) * 64 + c] = __float2half(s3); d_xr[(size_t)(r0 + 3) * 64 + c] = __float2half(t3); }
    }
}

// ---------------- edge pass: 4 edges per warp iteration, paired ep loads ----------------
__global__ __launch_bounds__(256)
void edge_pass_k(const int* __restrict__ ei, const float* __restrict__ att,
                 const unsigned long long* __restrict__ ep) {
    const unsigned F = 0xffffffffu;
    unsigned lane = threadIdx.x & 31;
    float2 at = reinterpret_cast<const float2*>(att)[lane];

    int wid = (blockIdx.x * blockDim.x + threadIdx.x) >> 5;
    int nwarp = (gridDim.x * blockDim.x) >> 5;
    const __half2* xl2p = reinterpret_cast<const __half2*>(d_xl);
    const __half2* xr2p = reinterpret_cast<const __half2*>(d_xr);

    for (int i = wid; i < E2 / 4; i += nwarp) {
        int e0 = 4 * i;
        int4 sq, dq;
        if (e0 < EE) {
            sq = *reinterpret_cast<const int4*>(ei + e0);
            dq = *reinterpret_cast<const int4*>(ei + EE + e0);
        } else {
            int n = e0 - EE;
            sq = make_int4(n, n + 1, n + 2, n + 3);
            dq = sq;
        }
        // paired ep loads: one LDG.64 covers 2 edges
        unsigned long long q0 = ep[(size_t)(2 * i) * 32 + lane];
        unsigned long long q1 = ep[(size_t)(2 * i + 1) * 32 + lane];
        unsigned h00, h01, h10, h11;
        asm("mov.b64 {%0,%1}, %2;" : "=r"(h00), "=r"(h01) : "l"(q0));
        asm("mov.b64 {%0,%1}, %2;" : "=r"(h10), "=r"(h11) : "l"(q1));
        float2 ep0 = __half22float2(*reinterpret_cast<__half2*>(&h00));
        float2 ep1 = __half22float2(*reinterpret_cast<__half2*>(&h01));
        float2 ep2 = __half22float2(*reinterpret_cast<__half2*>(&h10));
        float2 ep3 = __half22float2(*reinterpret_cast<__half2*>(&h11));
        float2 xl0 = __half22float2(xl2p[(unsigned)sq.x * 32 + lane]);
        float2 xl1 = __half22float2(xl2p[(unsigned)sq.y * 32 + lane]);
        float2 xl2 = __half22float2(xl2p[(unsigned)sq.z * 32 + lane]);
        float2 xl3 = __half22float2(xl2p[(unsigned)sq.w * 32 + lane]);
        float2 xr0 = __half22float2(xr2p[(unsigned)dq.x * 32 + lane]);
        float2 xr1 = __half22float2(xr2p[(unsigned)dq.y * 32 + lane]);
        float2 xr2 = __half22float2(xr2p[(unsigned)dq.z * 32 + lane]);
        float2 xr3 = __half22float2(xr2p[(unsigned)dq.w * 32 + lane]);

        float m0x = xl0.x + xr0.x + ep0.x, m0y = xl0.y + xr0.y + ep0.y;
        float m1x = xl1.x + xr1.x + ep1.x, m1y = xl1.y + xr1.y + ep1.y;
        float m2x = xl2.x + xr2.x + ep2.x, m2y = xl2.y + xr2.y + ep2.y;
        float m3x = xl3.x + xr3.x + ep3.x, m3y = xl3.y + xr3.y + ep3.y;
        m0x = (m0x > 0.f) ? m0x : 0.2f * m0x;  m0y = (m0y > 0.f) ? m0y : 0.2f * m0y;
        m1x = (m1x > 0.f) ? m1x : 0.2f * m1x;  m1y = (m1y > 0.f) ? m1y : 0.2f * m1y;
        m2x = (m2x > 0.f) ? m2x : 0.2f * m2x;  m2y = (m2y > 0.f) ? m2y : 0.2f * m2y;
        m3x = (m3x > 0.f) ? m3x : 0.2f * m3x;  m3y = (m3y > 0.f) ? m3y : 0.2f * m3y;
        float s0 = m0x * at.x + m0y * at.y;
        float s1 = m1x * at.x + m1y * at.y;
        float s2 = m2x * at.x + m2y * at.y;
        float s3 = m3x * at.x + m3y * at.y;
        s0 += __shfl_xor_sync(F, s0, 1); s1 += __shfl_xor_sync(F, s1, 1);
        s2 += __shfl_xor_sync(F, s2, 1); s3 += __shfl_xor_sync(F, s3, 1);
        s0 += __shfl_xor_sync(F, s0, 2); s1 += __shfl_xor_sync(F, s1, 2);
        s2 += __shfl_xor_sync(F, s2, 2); s3 += __shfl_xor_sync(F, s3, 2);
        s0 += __shfl_xor_sync(F, s0, 4); s1 += __shfl_xor_sync(F, s1, 4);
        s2 += __shfl_xor_sync(F, s2, 4); s3 += __shfl_xor_sync(F, s3, 4);
        float z0 = __expf(s0);   // softmax without max-shift (scores O(1))
        float z1 = __expf(s1);
        float z2 = __expf(s2);
        float z3 = __expf(s3);

        red2(d_acc + (unsigned)dq.x * 64 + 2 * lane, z0 * xl0.x, z0 * xl0.y);
        red2(d_acc + (unsigned)dq.y * 64 + 2 * lane, z1 * xl1.x, z1 * xl1.y);
        red2(d_acc + (unsigned)dq.z * 64 + 2 * lane, z2 * xl2.x, z2 * xl2.y);
        red2(d_acc + (unsigned)dq.w * 64 + 2 * lane, z3 * xl3.x, z3 * xl3.y);
        if ((lane & 7) == 0) {
            unsigned h = lane >> 3;
            atomicAdd(&d_den[(unsigned)dq.x * 4 + h], z0);
            atomicAdd(&d_den[(unsigned)dq.y * 4 + h], z1);
            atomicAdd(&d_den[(unsigned)dq.z * 4 + h], z2);
            atomicAdd(&d_den[(unsigned)dq.w * 4 + h], z3);
        }
    }
}

// ---------------- finalize layer 1 fused with global mean pool ----------------
__global__ void node_out_pool_k(const float* __restrict__ bias, const int* __restrict__ batch) {
    int t = blockIdx.x * blockDim.x + threadIdx.x;
    if (t >= NN * 16) return;
    int node = t >> 4;
    int part = t & 15;
    float inv = 1.0f / d_den[node * 4 + (part >> 2)];
    float4 a = reinterpret_cast<const float4*>(d_acc)[t];
    float4 b = reinterpret_cast<const float4*>(bias)[part];
    float vx = fmaxf(a.x * inv + b.x, 0.0f);
    float vy = fmaxf(a.y * inv + b.y, 0.0f);
    float vz = fmaxf(a.z * inv + b.z, 0.0f);
    float vw = fmaxf(a.w * inv + b.w, 0.0f);
    int g = batch[node];
    red4(d_g + g * 64 + part * 4, vx, vy, vz, vw);
    if (part == 0) atomicAdd(&d_gc[g], 1.0f);
}

// ---------------- MLP head ----------------
__global__ void mlp_k(const float* __restrict__ W1, const float* __restrict__ b1,
                      const float* __restrict__ W2, const float* __restrict__ b2,
                      float* __restrict__ out) {
    __shared__ float gx[64];
    __shared__ float hh[128];
    int g = blockIdx.x;
    int t = threadIdx.x;
    if (t < 64) gx[t] = d_g[g * 64 + t] / fmaxf(d_gc[g], 1.0f);
    __syncthreads();
    float s = b1[t];
#pragma unroll
    for (int k = 0; k < 64; k++) s += gx[k] * W1[k * 128 + t];
    hh[t] = fmaxf(s, 0.0f);
    __syncthreads();
    float o = b2[t];
#pragma unroll
    for (int k = 0; k < 128; k++) o += hh[k] * W2[k * 128 + t];
    out[g * 128 + t] = o;
}

// ---------------- launch (single stream) ----------------
extern "C" void kernel_launch(void* const* d_in, const int* in_sizes, int n_in,
                              void* d_out, int out_size) {
    const float* x0     = (const float*)d_in[0];
    const int*   ei     = (const int*)d_in[1];
    const float* ea     = (const float*)d_in[2];
    const int*   batch  = (const int*)d_in[3];
    const float* l0Wl   = (const float*)d_in[4];
    const float* l0bl   = (const float*)d_in[5];
    const float* l0Wr   = (const float*)d_in[6];
    const float* l0br   = (const float*)d_in[7];
    const float* l0We   = (const float*)d_in[8];
    const float* l0att  = (const float*)d_in[9];
    const float* l0bias = (const float*)d_in[10];
    const float* l1Wl   = (const float*)d_in[11];
    const float* l1bl   = (const float*)d_in[12];
    const float* l1Wr   = (const float*)d_in[13];
    const float* l1br   = (const float*)d_in[14];
    const float* l1We   = (const float*)d_in[15];
    const float* l1att  = (const float*)d_in[16];
    const float* l1bias = (const float*)d_in[17];
    const float* W1     = (const float*)d_in[18];
    const float* b1     = (const float*)d_in[19];
    const float* W2     = (const float*)d_in[20];
    const float* b2     = (const float*)d_in[21];
    float* out = (float*)d_out;

    void *pcnt, *ploop, *pacc, *pden, *pg, *pgc, *pep0, *pep1;
    cudaGetSymbolAddress(&pcnt, d_cnt);
    cudaGetSymbolAddress(&ploop, d_loop);
    cudaGetSymbolAddress(&pacc, d_acc);
    cudaGetSymbolAddress(&pden, d_den);
    cudaGetSymbolAddress(&pg, d_g);
    cudaGetSymbolAddress(&pgc, d_gc);
    cudaGetSymbolAddress(&pep0, d_ep0);   // REAL device pointers for kernel args
    cudaGetSymbolAddress(&pep1, d_ep1);

    cudaMemsetAsync(pcnt, 0, NN * sizeof(float));
    cudaMemsetAsync(ploop, 0, NN * EDIM * sizeof(float));
    cudaMemsetAsync(pg, 0, GG * HID * sizeof(float));
    cudaMemsetAsync(pgc, 0, GG * sizeof(float));

    loop_accum_k<<<(EE + 255) / 256, 256>>>(ei, ea);

    // both layers' edge projections in one pass (packed f32x2 math, fp16 storage)
    ep_both_k<<<4096, 128>>>(ea, l0We, l1We);

    // ---- layer 0 ----
    node_proj_k<<<2048, 256>>>(x0, l0Wl, l0bl, l0Wr, l0br);
    cudaMemsetAsync(pacc, 0, (size_t)NN * HID * sizeof(float));
    cudaMemsetAsync(pden, 0, (size_t)NN * 4 * sizeof(float));
    edge_pass_k<<<2048, 256>>>(ei, l0att, (const unsigned long long*)pep0);

    // ---- layer 1 (layer-0 finalize fused into projection) ----
    node_proj_fused_k<<<2048, 256>>>(l0bias, l1Wl, l1bl, l1Wr, l1br);
    cudaMemsetAsync(pacc, 0, (size_t)NN * HID * sizeof(float));
    cudaMemsetAsync(pden, 0, (size_t)NN * 4 * sizeof(float));
    edge_pass_k<<<2048, 256>>>(ei, l1att, (const unsigned long long*)pep1);
    node_out_pool_k<<<(NN * 16 + 255) / 256, 256>>>(l1bias, batch);

    // ---- MLP ----
    mlp_k<<<GG, OUTD>>>(W1, b1, W2, b2, out);
}

// round 15
// speedup vs baseline: 6.4027x; 1.0366x over previous
#include <cuda_runtime.h>
#include <cuda_fp16.h>

#define NN 100000
#define EE 1600000
#define E2 (EE + NN)
#define NP (E2 / 2)
#define GG 64
#define HID 64
#define EDIM 16
#define OUTD 128

// ---------------- scratch (device globals; no allocation) ----------------
__device__ float d_cnt[NN];
__device__ float d_loop[NN * EDIM];
__device__ __half d_xl[NN * HID];
__device__ __half d_xr[NN * HID];
__device__ float d_acc[NN * HID];
__device__ float d_den[NN * 4];
__device__ float d_g[GG * HID];
__device__ float d_gc[GG];
// pair-interleaved ep: ep[pair*32+lane] = u64{ half2(edge0 ch2l,2l+1), half2(edge1) }
__device__ unsigned long long d_ep0[(size_t)NP * 32];
__device__ unsigned long long d_ep1[(size_t)NP * 32];

__device__ __forceinline__ void red4(float* p, float a, float b, float c, float d) {
    asm volatile("red.global.add.v4.f32 [%0], {%1,%2,%3,%4};"
                 :: "l"(p), "f"(a), "f"(b), "f"(c), "f"(d) : "memory");
}
__device__ __forceinline__ void red2(float* p, float a, float b) {
    asm volatile("red.global.add.v2.f32 [%0], {%1,%2};"
                 :: "l"(p), "f"(a), "f"(b) : "memory");
}
__device__ __forceinline__ void red1(float* p, float a) {
    asm volatile("red.global.add.f32 [%0], %1;" :: "l"(p), "f"(a) : "memory");
}
// packed f32x2 helpers
__device__ __forceinline__ unsigned long long packdup(float a) {
    unsigned long long r;
    asm("mov.b64 %0, {%1, %1};" : "=l"(r) : "f"(a));
    return r;
}
__device__ __forceinline__ void ffma2(unsigned long long& acc, unsigned long long a,
                                      unsigned long long b) {
    asm("fma.rn.f32x2 %0, %1, %2, %3;" : "=l"(acc) : "l"(a), "l"(b), "l"(acc));
}
__device__ __forceinline__ unsigned pack_h2(unsigned long long acc) {
    float x, y;
    asm("mov.b64 {%0, %1}, %2;" : "=f"(x), "=f"(y) : "l"(acc));
    __half2 h = __floats2half2_rn(x, y);
    return *reinterpret_cast<unsigned*>(&h);
}

// ---------------- edge projections (real edges) + fused self-loop attr accumulation ----------------
// Warp handles a real-edge pair; 32 shuffle broadcasts shared across layers;
// MACs are FFMA2. While ea is in lanes, scatter-add it to d_loop[dst] (+cnt):
// this REPLACES the separate loop_accum pass (one less ea stream read).
__global__ void ep_both_k(const float* __restrict__ ea, const int* __restrict__ ei,
                          const float* __restrict__ We0, const float* __restrict__ We1) {
    const unsigned F = 0xffffffffu;
    int lane = threadIdx.x & 31;
    unsigned long long w0[EDIM], w1[EDIM];
    const unsigned long long* We0q = reinterpret_cast<const unsigned long long*>(We0);
    const unsigned long long* We1q = reinterpret_cast<const unsigned long long*>(We1);
#pragma unroll
    for (int k = 0; k < EDIM; k++) {
        w0[k] = We0q[k * 32 + lane];   // (We[k][2l], We[k][2l+1]) packed
        w1[k] = We1q[k * 32 + lane];
    }

    int wid = (blockIdx.x * blockDim.x + threadIdx.x) >> 5;
    int nwarp = (gridDim.x * blockDim.x) >> 5;

    for (int i = wid; i < EE / 2; i += nwarp) {
        int e0 = 2 * i;
        float av = ea[(size_t)e0 * EDIM + lane];   // lanes 0-15: edge e0; 16-31: e0+1
        int2 dp = *reinterpret_cast<const int2*>(ei + EE + e0);

        // fused loop_accum: lanes 0-15 add edge0's attrs to d_loop[dst0], 16-31 edge1
        int dst = (lane < 16) ? dp.x : dp.y;
        red1(&d_loop[(unsigned)dst * EDIM + (lane & 15)], av);
        if (lane == 0)  red1(&d_cnt[dp.x], 1.0f);
        if (lane == 16) red1(&d_cnt[dp.y], 1.0f);

        unsigned long long a00 = 0ull, a01 = 0ull, a10 = 0ull, a11 = 0ull;
#pragma unroll
        for (int k = 0; k < EDIM; k++) {
            unsigned long long p0 = packdup(__shfl_sync(F, av, k));
            unsigned long long p1 = packdup(__shfl_sync(F, av, k + 16));
            ffma2(a00, p0, w0[k]);
            ffma2(a01, p0, w1[k]);
            ffma2(a10, p1, w0[k]);
            ffma2(a11, p1, w1[k]);
        }
        unsigned long long v0, v1;
        asm("mov.b64 %0, {%1,%2};" : "=l"(v0) : "r"(pack_h2(a00)), "r"(pack_h2(a10)));
        asm("mov.b64 %0, {%1,%2};" : "=l"(v1) : "r"(pack_h2(a01)), "r"(pack_h2(a11)));
        d_ep0[(size_t)i * 32 + lane] = v0;
        d_ep1[(size_t)i * 32 + lane] = v1;
    }
}

// ---------------- self-loop edge projections (needs completed d_loop/d_cnt) ----------------
__global__ void self_ep_k(const float* __restrict__ We0, const float* __restrict__ We1) {
    const unsigned F = 0xffffffffu;
    int lane = threadIdx.x & 31;
    unsigned long long w0[EDIM], w1[EDIM];
    const unsigned long long* We0q = reinterpret_cast<const unsigned long long*>(We0);
    const unsigned long long* We1q = reinterpret_cast<const unsigned long long*>(We1);
#pragma unroll
    for (int k = 0; k < EDIM; k++) {
        w0[k] = We0q[k * 32 + lane];
        w1[k] = We1q[k * 32 + lane];
    }
    int wid = (blockIdx.x * blockDim.x + threadIdx.x) >> 5;
    int nwarp = (gridDim.x * blockDim.x) >> 5;

    for (int i = wid; i < NN / 2; i += nwarp) {
        int n0 = 2 * i;                       // self-loop pair: nodes n0, n0+1
        int n = n0 + (lane >> 4);
        float av = d_loop[(unsigned)n0 * EDIM + lane] / fmaxf(d_cnt[n], 1.0f);
        unsigned long long a00 = 0ull, a01 = 0ull, a10 = 0ull, a11 = 0ull;
#pragma unroll
        for (int k = 0; k < EDIM; k++) {
            unsigned long long p0 = packdup(__shfl_sync(F, av, k));
            unsigned long long p1 = packdup(__shfl_sync(F, av, k + 16));
            ffma2(a00, p0, w0[k]);
            ffma2(a01, p0, w1[k]);
            ffma2(a10, p1, w0[k]);
            ffma2(a11, p1, w1[k]);
        }
        unsigned long long v0, v1;
        asm("mov.b64 %0, {%1,%2};" : "=l"(v0) : "r"(pack_h2(a00)), "r"(pack_h2(a10)));
        asm("mov.b64 %0, {%1,%2};" : "=l"(v1) : "r"(pack_h2(a01)), "r"(pack_h2(a11)));
        size_t pi = (size_t)(EE / 2) + i;     // pair index in the global pair array
        d_ep0[pi * 32 + lane] = v0;
        d_ep1[pi * 32 + lane] = v1;
    }
}

// ---------------- node projections (layer 0), 8-row register blocking ----------------
__global__ void node_proj_k(const float* __restrict__ x,
                            const float* __restrict__ Wl, const float* __restrict__ bl,
                            const float* __restrict__ Wr, const float* __restrict__ br) {
    __shared__ float sWl[64 * 64];
    __shared__ float sWr[64 * 64];
    __shared__ float sx[32 * 64];
    for (int i = threadIdx.x; i < 64 * 16; i += blockDim.x) {
        reinterpret_cast<float4*>(sWl)[i] = reinterpret_cast<const float4*>(Wl)[i];
        reinterpret_cast<float4*>(sWr)[i] = reinterpret_cast<const float4*>(Wr)[i];
    }
    int c  = threadIdx.x & 63;
    int rl = threadIdx.x >> 6;   // 0..3 -> rows rl*8 .. rl*8+7
    float blc = bl[c], brc = br[c];
    for (int base = blockIdx.x * 32; base < NN; base += gridDim.x * 32) {
        __syncthreads();
        for (int i = threadIdx.x; i < 32 * 16; i += 256) {
            int r = base + (i >> 4);
            reinterpret_cast<float4*>(sx)[i] = (r < NN)
                ? reinterpret_cast<const float4*>(x)[(size_t)r * 16 + (i & 15)]
                : make_float4(0.f, 0.f, 0.f, 0.f);
        }
        __syncthreads();
        float s[8], t[8];
#pragma unroll
        for (int j = 0; j < 8; j++) { s[j] = blc; t[j] = brc; }
        const float* xrow = sx + rl * 8 * 64;
#pragma unroll
        for (int k = 0; k < 64; k++) {
            float wl = sWl[k * 64 + c];
            float wr = sWr[k * 64 + c];
#pragma unroll
            for (int j = 0; j < 8; j++) {
                float xv = xrow[j * 64 + k];
                s[j] += xv * wl;
                t[j] += xv * wr;
            }
        }
        int r0 = base + rl * 8;
#pragma unroll
        for (int j = 0; j < 8; j++) {
            if (r0 + j < NN) {
                d_xl[(size_t)(r0 + j) * 64 + c] = __float2half(s[j]);
                d_xr[(size_t)(r0 + j) * 64 + c] = __float2half(t[j]);
            }
        }
    }
}

// ---------------- node projection (layer 1): fuses layer-0 finalize, 8-row blocking ----------------
__global__ void node_proj_fused_k(const float* __restrict__ bias0,
                                  const float* __restrict__ Wl, const float* __restrict__ bl,
                                  const float* __restrict__ Wr, const float* __restrict__ br) {
    __shared__ float sWl[64 * 64];
    __shared__ float sWr[64 * 64];
    __shared__ float sx[32 * 64];
    for (int i = threadIdx.x; i < 64 * 16; i += blockDim.x) {
        reinterpret_cast<float4*>(sWl)[i] = reinterpret_cast<const float4*>(Wl)[i];
        reinterpret_cast<float4*>(sWr)[i] = reinterpret_cast<const float4*>(Wr)[i];
    }
    int c  = threadIdx.x & 63;
    int rl = threadIdx.x >> 6;
    float blc = bl[c], brc = br[c];
    for (int base = blockIdx.x * 32; base < NN; base += gridDim.x * 32) {
        __syncthreads();
        for (int i = threadIdx.x; i < 32 * 16; i += 256) {
            int r = base + (i >> 4);
            int part = i & 15;
            float4 v = make_float4(0.f, 0.f, 0.f, 0.f);
            if (r < NN) {
                float inv = 1.0f / d_den[r * 4 + (part >> 2)];
                float4 a = reinterpret_cast<const float4*>(d_acc)[(size_t)r * 16 + part];
                float4 b = reinterpret_cast<const float4*>(bias0)[part];
                v.x = fmaxf(a.x * inv + b.x, 0.0f);
                v.y = fmaxf(a.y * inv + b.y, 0.0f);
                v.z = fmaxf(a.z * inv + b.z, 0.0f);
                v.w = fmaxf(a.w * inv + b.w, 0.0f);
            }
            reinterpret_cast<float4*>(sx)[i] = v;
        }
        __syncthreads();
        float s[8], t[8];
#pragma unroll
        for (int j = 0; j < 8; j++) { s[j] = blc; t[j] = brc; }
        const float* xrow = sx + rl * 8 * 64;
#pragma unroll
        for (int k = 0; k < 64; k++) {
            float wl = sWl[k * 64 + c];
            float wr = sWr[k * 64 + c];
#pragma unroll
            for (int j = 0; j < 8; j++) {
                float xv = xrow[j * 64 + k];
                s[j] += xv * wl;
                t[j] += xv * wr;
            }
        }
        int r0 = base + rl * 8;
#pragma unroll
        for (int j = 0; j < 8; j++) {
            if (r0 + j < NN) {
                d_xl[(size_t)(r0 + j) * 64 + c] = __float2half(s[j]);
                d_xr[(size_t)(r0 + j) * 64 + c] = __float2half(t[j]);
            }
        }
    }
}

// ---------------- edge pass: 4 edges per warp iteration, paired ep loads ----------------
__global__ __launch_bounds__(256)
void edge_pass_k(const int* __restrict__ ei, const float* __restrict__ att,
                 const unsigned long long* __restrict__ ep) {
    const unsigned F = 0xffffffffu;
    unsigned lane = threadIdx.x & 31;
    float2 at = reinterpret_cast<const float2*>(att)[lane];

    int wid = (blockIdx.x * blockDim.x + threadIdx.x) >> 5;
    int nwarp = (gridDim.x * blockDim.x) >> 5;
    const __half2* xl2p = reinterpret_cast<const __half2*>(d_xl);
    const __half2* xr2p = reinterpret_cast<const __half2*>(d_xr);

    for (int i = wid; i < E2 / 4; i += nwarp) {
        int e0 = 4 * i;
        int4 sq, dq;
        if (e0 < EE) {
            sq = *reinterpret_cast<const int4*>(ei + e0);
            dq = *reinterpret_cast<const int4*>(ei + EE + e0);
        } else {
            int n = e0 - EE;
            sq = make_int4(n, n + 1, n + 2, n + 3);
            dq = sq;
        }
        unsigned long long q0 = ep[(size_t)(2 * i) * 32 + lane];
        unsigned long long q1 = ep[(size_t)(2 * i + 1) * 32 + lane];
        unsigned h00, h01, h10, h11;
        asm("mov.b64 {%0,%1}, %2;" : "=r"(h00), "=r"(h01) : "l"(q0));
        asm("mov.b64 {%0,%1}, %2;" : "=r"(h10), "=r"(h11) : "l"(q1));
        float2 ep0 = __half22float2(*reinterpret_cast<__half2*>(&h00));
        float2 ep1 = __half22float2(*reinterpret_cast<__half2*>(&h01));
        float2 ep2 = __half22float2(*reinterpret_cast<__half2*>(&h10));
        float2 ep3 = __half22float2(*reinterpret_cast<__half2*>(&h11));
        float2 xl0 = __half22float2(xl2p[(unsigned)sq.x * 32 + lane]);
        float2 xl1 = __half22float2(xl2p[(unsigned)sq.y * 32 + lane]);
        float2 xl2 = __half22float2(xl2p[(unsigned)sq.z * 32 + lane]);
        float2 xl3 = __half22float2(xl2p[(unsigned)sq.w * 32 + lane]);
        float2 xr0 = __half22float2(xr2p[(unsigned)dq.x * 32 + lane]);
        float2 xr1 = __half22float2(xr2p[(unsigned)dq.y * 32 + lane]);
        float2 xr2 = __half22float2(xr2p[(unsigned)dq.z * 32 + lane]);
        float2 xr3 = __half22float2(xr2p[(unsigned)dq.w * 32 + lane]);

        float m0x = xl0.x + xr0.x + ep0.x, m0y = xl0.y + xr0.y + ep0.y;
        float m1x = xl1.x + xr1.x + ep1.x, m1y = xl1.y + xr1.y + ep1.y;
        float m2x = xl2.x + xr2.x + ep2.x, m2y = xl2.y + xr2.y + ep2.y;
        float m3x = xl3.x + xr3.x + ep3.x, m3y = xl3.y + xr3.y + ep3.y;
        m0x = (m0x > 0.f) ? m0x : 0.2f * m0x;  m0y = (m0y > 0.f) ? m0y : 0.2f * m0y;
        m1x = (m1x > 0.f) ? m1x : 0.2f * m1x;  m1y = (m1y > 0.f) ? m1y : 0.2f * m1y;
        m2x = (m2x > 0.f) ? m2x : 0.2f * m2x;  m2y = (m2y > 0.f) ? m2y : 0.2f * m2y;
        m3x = (m3x > 0.f) ? m3x : 0.2f * m3x;  m3y = (m3y > 0.f) ? m3y : 0.2f * m3y;
        float s0 = m0x * at.x + m0y * at.y;
        float s1 = m1x * at.x + m1y * at.y;
        float s2 = m2x * at.x + m2y * at.y;
        float s3 = m3x * at.x + m3y * at.y;
        s0 += __shfl_xor_sync(F, s0, 1); s1 += __shfl_xor_sync(F, s1, 1);
        s2 += __shfl_xor_sync(F, s2, 1); s3 += __shfl_xor_sync(F, s3, 1);
        s0 += __shfl_xor_sync(F, s0, 2); s1 += __shfl_xor_sync(F, s1, 2);
        s2 += __shfl_xor_sync(F, s2, 2); s3 += __shfl_xor_sync(F, s3, 2);
        s0 += __shfl_xor_sync(F, s0, 4); s1 += __shfl_xor_sync(F, s1, 4);
        s2 += __shfl_xor_sync(F, s2, 4); s3 += __shfl_xor_sync(F, s3, 4);
        float z0 = __expf(s0);   // softmax without max-shift (scores O(1))
        float z1 = __expf(s1);
        float z2 = __expf(s2);
        float z3 = __expf(s3);

        red2(d_acc + (unsigned)dq.x * 64 + 2 * lane, z0 * xl0.x, z0 * xl0.y);
        red2(d_acc + (unsigned)dq.y * 64 + 2 * lane, z1 * xl1.x, z1 * xl1.y);
        red2(d_acc + (unsigned)dq.z * 64 + 2 * lane, z2 * xl2.x, z2 * xl2.y);
        red2(d_acc + (unsigned)dq.w * 64 + 2 * lane, z3 * xl3.x, z3 * xl3.y);
        if ((lane & 7) == 0) {
            unsigned h = lane >> 3;
            atomicAdd(&d_den[(unsigned)dq.x * 4 + h], z0);
            atomicAdd(&d_den[(unsigned)dq.y * 4 + h], z1);
            atomicAdd(&d_den[(unsigned)dq.z * 4 + h], z2);
            atomicAdd(&d_den[(unsigned)dq.w * 4 + h], z3);
        }
    }
}

// ---------------- finalize layer 1 fused with global mean pool ----------------
__global__ void node_out_pool_k(const float* __restrict__ bias, const int* __restrict__ batch) {
    int t = blockIdx.x * blockDim.x + threadIdx.x;
    if (t >= NN * 16) return;
    int node = t >> 4;
    int part = t & 15;
    float inv = 1.0f / d_den[node * 4 + (part >> 2)];
    float4 a = reinterpret_cast<const float4*>(d_acc)[t];
    float4 b = reinterpret_cast<const float4*>(bias)[part];
    float vx = fmaxf(a.x * inv + b.x, 0.0f);
    float vy = fmaxf(a.y * inv + b.y, 0.0f);
    float vz = fmaxf(a.z * inv + b.z, 0.0f);
    float vw = fmaxf(a.w * inv + b.w, 0.0f);
    int g = batch[node];
    red4(d_g + g * 64 + part * 4, vx, vy, vz, vw);
    if (part == 0) atomicAdd(&d_gc[g], 1.0f);
}

// ---------------- MLP head ----------------
__global__ void mlp_k(const float* __restrict__ W1, const float* __restrict__ b1,
                      const float* __restrict__ W2, const float* __restrict__ b2,
                      float* __restrict__ out) {
    __shared__ float gx[64];
    __shared__ float hh[128];
    int g = blockIdx.x;
    int t = threadIdx.x;
    if (t < 64) gx[t] = d_g[g * 64 + t] / fmaxf(d_gc[g], 1.0f);
    __syncthreads();
    float s = b1[t];
#pragma unroll
    for (int k = 0; k < 64; k++) s += gx[k] * W1[k * 128 + t];
    hh[t] = fmaxf(s, 0.0f);
    __syncthreads();
    float o = b2[t];
#pragma unroll
    for (int k = 0; k < 128; k++) o += hh[k] * W2[k * 128 + t];
    out[g * 128 + t] = o;
}

// ---------------- launch (single stream) ----------------
extern "C" void kernel_launch(void* const* d_in, const int* in_sizes, int n_in,
                              void* d_out, int out_size) {
    const float* x0     = (const float*)d_in[0];
    const int*   ei     = (const int*)d_in[1];
    const float* ea     = (const float*)d_in[2];
    const int*   batch  = (const int*)d_in[3];
    const float* l0Wl   = (const float*)d_in[4];
    const float* l0bl   = (const float*)d_in[5];
    const float* l0Wr   = (const float*)d_in[6];
    const float* l0br   = (const float*)d_in[7];
    const float* l0We   = (const float*)d_in[8];
    const float* l0att  = (const float*)d_in[9];
    const float* l0bias = (const float*)d_in[10];
    const float* l1Wl   = (const float*)d_in[11];
    const float* l1bl   = (const float*)d_in[12];
    const float* l1Wr   = (const float*)d_in[13];
    const float* l1br   = (const float*)d_in[14];
    const float* l1We   = (const float*)d_in[15];
    const float* l1att  = (const float*)d_in[16];
    const float* l1bias = (const float*)d_in[17];
    const float* W1     = (const float*)d_in[18];
    const float* b1     = (const float*)d_in[19];
    const float* W2     = (const float*)d_in[20];
    const float* b2     = (const float*)d_in[21];
    float* out = (float*)d_out;

    void *pcnt, *ploop, *pacc, *pden, *pg, *pgc, *pep0, *pep1;
    cudaGetSymbolAddress(&pcnt, d_cnt);
    cudaGetSymbolAddress(&ploop, d_loop);
    cudaGetSymbolAddress(&pacc, d_acc);
    cudaGetSymbolAddress(&pden, d_den);
    cudaGetSymbolAddress(&pg, d_g);
    cudaGetSymbolAddress(&pgc, d_gc);
    cudaGetSymbolAddress(&pep0, d_ep0);   // REAL device pointers for kernel args
    cudaGetSymbolAddress(&pep1, d_ep1);

    cudaMemsetAsync(pcnt, 0, NN * sizeof(float));
    cudaMemsetAsync(ploop, 0, NN * EDIM * sizeof(float));
    cudaMemsetAsync(pg, 0, GG * HID * sizeof(float));
    cudaMemsetAsync(pgc, 0, GG * sizeof(float));

    // real-edge ep for both layers + fused self-loop attr accumulation
    ep_both_k<<<4096, 128>>>(ea, ei, l0We, l1We);
    // self-loop ep (needs completed d_loop/d_cnt)
    self_ep_k<<<512, 128>>>(l0We, l1We);

    // ---- layer 0 ----
    node_proj_k<<<2048, 256>>>(x0, l0Wl, l0bl, l0Wr, l0br);
    cudaMemsetAsync(pacc, 0, (size_t)NN * HID * sizeof(float));
    cudaMemsetAsync(pden, 0, (size_t)NN * 4 * sizeof(float));
    edge_pass_k<<<2048, 256>>>(ei, l0att, (const unsigned long long*)pep0);

    // ---- layer 1 (layer-0 finalize fused into projection) ----
    node_proj_fused_k<<<2048, 256>>>(l0bias, l1Wl, l1bl, l1Wr, l1br);
    cudaMemsetAsync(pacc, 0, (size_t)NN * HID * sizeof(float));
    cudaMemsetAsync(pden, 0, (size_t)NN * 4 * sizeof(float));
    edge_pass_k<<<2048, 256>>>(ei, l1att, (const unsigned long long*)pep1);
    node_out_pool_k<<<(NN * 16 + 255) / 256, 256>>>(l1bias, batch);

    // ---- MLP ----
    mlp_k<<<GG, OUTD>>>(W1, b1, W2, b2, out);
}

// round 16
// speedup vs baseline: 6.5049x; 1.0160x over previous
#include <cuda_runtime.h>
#include <cuda_fp16.h>

#define NN 100000
#define EE 1600000
#define E2 (EE + NN)
#define NP (E2 / 2)
#define GG 64
#define HID 64
#define EDIM 16
#define OUTD 128

// ---------------- scratch (device globals; no allocation) ----------------
__device__ float d_cnt[NN];
__device__ float d_loop[NN * EDIM];
__device__ __half d_xl[NN * HID];
__device__ __half d_xr[NN * HID];
__device__ float d_acc[NN * HID];
__device__ float d_den[NN * 4];
__device__ float d_g[GG * HID];
__device__ float d_gc[GG];
// pair-interleaved ep: ep[pair*32+lane] = u64{ half2(edge0 ch2l,2l+1), half2(edge1) }
__device__ unsigned long long d_ep0[(size_t)NP * 32];
__device__ unsigned long long d_ep1[(size_t)NP * 32];

__device__ __forceinline__ void red4(float* p, float a, float b, float c, float d) {
    asm volatile("red.global.add.v4.f32 [%0], {%1,%2,%3,%4};"
                 :: "l"(p), "f"(a), "f"(b), "f"(c), "f"(d) : "memory");
}
__device__ __forceinline__ void red2(float* p, float a, float b) {
    asm volatile("red.global.add.v2.f32 [%0], {%1,%2};"
                 :: "l"(p), "f"(a), "f"(b) : "memory");
}
__device__ __forceinline__ void red1(float* p, float a) {
    asm volatile("red.global.add.f32 [%0], %1;" :: "l"(p), "f"(a) : "memory");
}
// packed f32x2 helpers
__device__ __forceinline__ unsigned long long packdup(float a) {
    unsigned long long r;
    asm("mov.b64 %0, {%1, %1};" : "=l"(r) : "f"(a));
    return r;
}
__device__ __forceinline__ void ffma2(unsigned long long& acc, unsigned long long a,
                                      unsigned long long b) {
    asm("fma.rn.f32x2 %0, %1, %2, %3;" : "=l"(acc) : "l"(a), "l"(b), "l"(acc));
}
__device__ __forceinline__ unsigned pack_h2(unsigned long long acc) {
    float x, y;
    asm("mov.b64 {%0, %1}, %2;" : "=f"(x), "=f"(y) : "l"(acc));
    __half2 h = __floats2half2_rn(x, y);
    return *reinterpret_cast<unsigned*>(&h);
}

// ---------------- edge projections (real edges) + fused self-loop attr accumulation ----------------
__global__ void ep_both_k(const float* __restrict__ ea, const int* __restrict__ ei,
                          const float* __restrict__ We0, const float* __restrict__ We1) {
    const unsigned F = 0xffffffffu;
    int lane = threadIdx.x & 31;
    unsigned long long w0[EDIM], w1[EDIM];
    const unsigned long long* We0q = reinterpret_cast<const unsigned long long*>(We0);
    const unsigned long long* We1q = reinterpret_cast<const unsigned long long*>(We1);
#pragma unroll
    for (int k = 0; k < EDIM; k++) {
        w0[k] = We0q[k * 32 + lane];
        w1[k] = We1q[k * 32 + lane];
    }

    int wid = (blockIdx.x * blockDim.x + threadIdx.x) >> 5;
    int nwarp = (gridDim.x * blockDim.x) >> 5;

    for (int i = wid; i < EE / 2; i += nwarp) {
        int e0 = 2 * i;
        float av = ea[(size_t)e0 * EDIM + lane];   // lanes 0-15: edge e0; 16-31: e0+1
        int2 dp = *reinterpret_cast<const int2*>(ei + EE + e0);

        int dst = (lane < 16) ? dp.x : dp.y;
        red1(&d_loop[(unsigned)dst * EDIM + (lane & 15)], av);
        if (lane == 0)  red1(&d_cnt[dp.x], 1.0f);
        if (lane == 16) red1(&d_cnt[dp.y], 1.0f);

        unsigned long long a00 = 0ull, a01 = 0ull, a10 = 0ull, a11 = 0ull;
#pragma unroll
        for (int k = 0; k < EDIM; k++) {
            unsigned long long p0 = packdup(__shfl_sync(F, av, k));
            unsigned long long p1 = packdup(__shfl_sync(F, av, k + 16));
            ffma2(a00, p0, w0[k]);
            ffma2(a01, p0, w1[k]);
            ffma2(a10, p1, w0[k]);
            ffma2(a11, p1, w1[k]);
        }
        unsigned long long v0, v1;
        asm("mov.b64 %0, {%1,%2};" : "=l"(v0) : "r"(pack_h2(a00)), "r"(pack_h2(a10)));
        asm("mov.b64 %0, {%1,%2};" : "=l"(v1) : "r"(pack_h2(a01)), "r"(pack_h2(a11)));
        d_ep0[(size_t)i * 32 + lane] = v0;
        d_ep1[(size_t)i * 32 + lane] = v1;
    }
}

// ---------------- self-loop edge projections (needs completed d_loop/d_cnt) ----------------
__global__ void self_ep_k(const float* __restrict__ We0, const float* __restrict__ We1) {
    const unsigned F = 0xffffffffu;
    int lane = threadIdx.x & 31;
    unsigned long long w0[EDIM], w1[EDIM];
    const unsigned long long* We0q = reinterpret_cast<const unsigned long long*>(We0);
    const unsigned long long* We1q = reinterpret_cast<const unsigned long long*>(We1);
#pragma unroll
    for (int k = 0; k < EDIM; k++) {
        w0[k] = We0q[k * 32 + lane];
        w1[k] = We1q[k * 32 + lane];
    }
    int wid = (blockIdx.x * blockDim.x + threadIdx.x) >> 5;
    int nwarp = (gridDim.x * blockDim.x) >> 5;

    for (int i = wid; i < NN / 2; i += nwarp) {
        int n0 = 2 * i;
        int n = n0 + (lane >> 4);
        float av = d_loop[(unsigned)n0 * EDIM + lane] / fmaxf(d_cnt[n], 1.0f);
        unsigned long long a00 = 0ull, a01 = 0ull, a10 = 0ull, a11 = 0ull;
#pragma unroll
        for (int k = 0; k < EDIM; k++) {
            unsigned long long p0 = packdup(__shfl_sync(F, av, k));
            unsigned long long p1 = packdup(__shfl_sync(F, av, k + 16));
            ffma2(a00, p0, w0[k]);
            ffma2(a01, p0, w1[k]);
            ffma2(a10, p1, w0[k]);
            ffma2(a11, p1, w1[k]);
        }
        unsigned long long v0, v1;
        asm("mov.b64 %0, {%1,%2};" : "=l"(v0) : "r"(pack_h2(a00)), "r"(pack_h2(a10)));
        asm("mov.b64 %0, {%1,%2};" : "=l"(v1) : "r"(pack_h2(a01)), "r"(pack_h2(a11)));
        size_t pi = (size_t)(EE / 2) + i;
        d_ep0[pi * 32 + lane] = v0;
        d_ep1[pi * 32 + lane] = v1;
    }
}

// ---------------- node projections (layer 0), 8-row register blocking ----------------
__global__ void node_proj_k(const float* __restrict__ x,
                            const float* __restrict__ Wl, const float* __restrict__ bl,
                            const float* __restrict__ Wr, const float* __restrict__ br) {
    __shared__ float sWl[64 * 64];
    __shared__ float sWr[64 * 64];
    __shared__ float sx[32 * 64];
    for (int i = threadIdx.x; i < 64 * 16; i += blockDim.x) {
        reinterpret_cast<float4*>(sWl)[i] = reinterpret_cast<const float4*>(Wl)[i];
        reinterpret_cast<float4*>(sWr)[i] = reinterpret_cast<const float4*>(Wr)[i];
    }
    int c  = threadIdx.x & 63;
    int rl = threadIdx.x >> 6;
    float blc = bl[c], brc = br[c];
    for (int base = blockIdx.x * 32; base < NN; base += gridDim.x * 32) {
        __syncthreads();
        for (int i = threadIdx.x; i < 32 * 16; i += 256) {
            int r = base + (i >> 4);
            reinterpret_cast<float4*>(sx)[i] = (r < NN)
                ? reinterpret_cast<const float4*>(x)[(size_t)r * 16 + (i & 15)]
                : make_float4(0.f, 0.f, 0.f, 0.f);
        }
        __syncthreads();
        float s[8], t[8];
#pragma unroll
        for (int j = 0; j < 8; j++) { s[j] = blc; t[j] = brc; }
        const float* xrow = sx + rl * 8 * 64;
#pragma unroll
        for (int k = 0; k < 64; k++) {
            float wl = sWl[k * 64 + c];
            float wr = sWr[k * 64 + c];
#pragma unroll
            for (int j = 0; j < 8; j++) {
                float xv = xrow[j * 64 + k];
                s[j] += xv * wl;
                t[j] += xv * wr;
            }
        }
        int r0 = base + rl * 8;
#pragma unroll
        for (int j = 0; j < 8; j++) {
            if (r0 + j < NN) {
                d_xl[(size_t)(r0 + j) * 64 + c] = __float2half(s[j]);
                d_xr[(size_t)(r0 + j) * 64 + c] = __float2half(t[j]);
            }
        }
    }
}

// ---------------- node projection (layer 1): fuses layer-0 finalize, 8-row blocking ----------------
__global__ void node_proj_fused_k(const float* __restrict__ bias0,
                                  const float* __restrict__ Wl, const float* __restrict__ bl,
                                  const float* __restrict__ Wr, const float* __restrict__ br) {
    __shared__ float sWl[64 * 64];
    __shared__ float sWr[64 * 64];
    __shared__ float sx[32 * 64];
    for (int i = threadIdx.x; i < 64 * 16; i += blockDim.x) {
        reinterpret_cast<float4*>(sWl)[i] = reinterpret_cast<const float4*>(Wl)[i];
        reinterpret_cast<float4*>(sWr)[i] = reinterpret_cast<const float4*>(Wr)[i];
    }
    int c  = threadIdx.x & 63;
    int rl = threadIdx.x >> 6;
    float blc = bl[c], brc = br[c];
    for (int base = blockIdx.x * 32; base < NN; base += gridDim.x * 32) {
        __syncthreads();
        for (int i = threadIdx.x; i < 32 * 16; i += 256) {
            int r = base + (i >> 4);
            int part = i & 15;
            float4 v = make_float4(0.f, 0.f, 0.f, 0.f);
            if (r < NN) {
                float inv = 1.0f / d_den[r * 4 + (part >> 2)];
                float4 a = reinterpret_cast<const float4*>(d_acc)[(size_t)r * 16 + part];
                float4 b = reinterpret_cast<const float4*>(bias0)[part];
                v.x = fmaxf(a.x * inv + b.x, 0.0f);
                v.y = fmaxf(a.y * inv + b.y, 0.0f);
                v.z = fmaxf(a.z * inv + b.z, 0.0f);
                v.w = fmaxf(a.w * inv + b.w, 0.0f);
            }
            reinterpret_cast<float4*>(sx)[i] = v;
        }
        __syncthreads();
        float s[8], t[8];
#pragma unroll
        for (int j = 0; j < 8; j++) { s[j] = blc; t[j] = brc; }
        const float* xrow = sx + rl * 8 * 64;
#pragma unroll
        for (int k = 0; k < 64; k++) {
            float wl = sWl[k * 64 + c];
            float wr = sWr[k * 64 + c];
#pragma unroll
            for (int j = 0; j < 8; j++) {
                float xv = xrow[j * 64 + k];
                s[j] += xv * wl;
                t[j] += xv * wr;
            }
        }
        int r0 = base + rl * 8;
#pragma unroll
        for (int j = 0; j < 8; j++) {
            if (r0 + j < NN) {
                d_xl[(size_t)(r0 + j) * 64 + c] = __float2half(s[j]);
                d_xr[(size_t)(r0 + j) * 64 + c] = __float2half(t[j]);
            }
        }
    }
}

// ---------------- edge pass: 8 edges per warp iteration ----------------
// Octet (8i..8i+7); lane l owns channels {2l,2l+1}; head = lane>>3.
// 24 loads in flight per warp iteration. EE and NN divisible by 8.
__global__ __launch_bounds__(256)
void edge_pass_k(const int* __restrict__ ei, const float* __restrict__ att,
                 const unsigned long long* __restrict__ ep) {
    const unsigned F = 0xffffffffu;
    unsigned lane = threadIdx.x & 31;
    float2 at = reinterpret_cast<const float2*>(att)[lane];

    int wid = (blockIdx.x * blockDim.x + threadIdx.x) >> 5;
    int nwarp = (gridDim.x * blockDim.x) >> 5;
    const __half2* xl2p = reinterpret_cast<const __half2*>(d_xl);
    const __half2* xr2p = reinterpret_cast<const __half2*>(d_xr);

    for (int i = wid; i < E2 / 8; i += nwarp) {
        int e0 = 8 * i;
        int s[8], d[8];
        if (e0 < EE) {
            int4 sa = *reinterpret_cast<const int4*>(ei + e0);
            int4 sb = *reinterpret_cast<const int4*>(ei + e0 + 4);
            int4 da = *reinterpret_cast<const int4*>(ei + EE + e0);
            int4 db = *reinterpret_cast<const int4*>(ei + EE + e0 + 4);
            s[0]=sa.x; s[1]=sa.y; s[2]=sa.z; s[3]=sa.w;
            s[4]=sb.x; s[5]=sb.y; s[6]=sb.z; s[7]=sb.w;
            d[0]=da.x; d[1]=da.y; d[2]=da.z; d[3]=da.w;
            d[4]=db.x; d[5]=db.y; d[6]=db.z; d[7]=db.w;
        } else {
            int n = e0 - EE;
#pragma unroll
            for (int j = 0; j < 8; j++) { s[j] = n + j; d[j] = n + j; }
        }
        // 4 paired ep loads cover 8 edges
        float2 epv[8];
#pragma unroll
        for (int j = 0; j < 4; j++) {
            unsigned long long q = ep[(size_t)(4 * i + j) * 32 + lane];
            unsigned ha, hb;
            asm("mov.b64 {%0,%1}, %2;" : "=r"(ha), "=r"(hb) : "l"(q));
            epv[2 * j]     = __half22float2(*reinterpret_cast<__half2*>(&ha));
            epv[2 * j + 1] = __half22float2(*reinterpret_cast<__half2*>(&hb));
        }
        float2 xl[8], xr[8];
#pragma unroll
        for (int j = 0; j < 8; j++) {
            xl[j] = __half22float2(xl2p[(unsigned)s[j] * 32 + lane]);
            xr[j] = __half22float2(xr2p[(unsigned)d[j] * 32 + lane]);
        }
        float sc[8];
#pragma unroll
        for (int j = 0; j < 8; j++) {
            float mx = xl[j].x + xr[j].x + epv[j].x;
            float my = xl[j].y + xr[j].y + epv[j].y;
            mx = (mx > 0.f) ? mx : 0.2f * mx;
            my = (my > 0.f) ? my : 0.2f * my;
            sc[j] = mx * at.x + my * at.y;
        }
#pragma unroll
        for (int j = 0; j < 8; j++) sc[j] += __shfl_xor_sync(F, sc[j], 1);
#pragma unroll
        for (int j = 0; j < 8; j++) sc[j] += __shfl_xor_sync(F, sc[j], 2);
#pragma unroll
        for (int j = 0; j < 8; j++) sc[j] += __shfl_xor_sync(F, sc[j], 4);
        float z[8];
#pragma unroll
        for (int j = 0; j < 8; j++) z[j] = __expf(sc[j]);   // softmax without max-shift

#pragma unroll
        for (int j = 0; j < 8; j++)
            red2(d_acc + (unsigned)d[j] * 64 + 2 * lane, z[j] * xl[j].x, z[j] * xl[j].y);
        if ((lane & 7) == 0) {
            unsigned h = lane >> 3;
#pragma unroll
            for (int j = 0; j < 8; j++)
                atomicAdd(&d_den[(unsigned)d[j] * 4 + h], z[j]);
        }
    }
}

// ---------------- finalize layer 1 fused with global mean pool ----------------
__global__ void node_out_pool_k(const float* __restrict__ bias, const int* __restrict__ batch) {
    int t = blockIdx.x * blockDim.x + threadIdx.x;
    if (t >= NN * 16) return;
    int node = t >> 4;
    int part = t & 15;
    float inv = 1.0f / d_den[node * 4 + (part >> 2)];
    float4 a = reinterpret_cast<const float4*>(d_acc)[t];
    float4 b = reinterpret_cast<const float4*>(bias)[part];
    float vx = fmaxf(a.x * inv + b.x, 0.0f);
    float vy = fmaxf(a.y * inv + b.y, 0.0f);
    float vz = fmaxf(a.z * inv + b.z, 0.0f);
    float vw = fmaxf(a.w * inv + b.w, 0.0f);
    int g = batch[node];
    red4(d_g + g * 64 + part * 4, vx, vy, vz, vw);
    if (part == 0) atomicAdd(&d_gc[g], 1.0f);
}

// ---------------- MLP head ----------------
__global__ void mlp_k(const float* __restrict__ W1, const float* __restrict__ b1,
                      const float* __restrict__ W2, const float* __restrict__ b2,
                      float* __restrict__ out) {
    __shared__ float gx[64];
    __shared__ float hh[128];
    int g = blockIdx.x;
    int t = threadIdx.x;
    if (t < 64) gx[t] = d_g[g * 64 + t] / fmaxf(d_gc[g], 1.0f);
    __syncthreads();
    float s = b1[t];
#pragma unroll
    for (int k = 0; k < 64; k++) s += gx[k] * W1[k * 128 + t];
    hh[t] = fmaxf(s, 0.0f);
    __syncthreads();
    float o = b2[t];
#pragma unroll
    for (int k = 0; k < 128; k++) o += hh[k] * W2[k * 128 + t];
    out[g * 128 + t] = o;
}

// ---------------- launch (single stream) ----------------
extern "C" void kernel_launch(void* const* d_in, const int* in_sizes, int n_in,
                              void* d_out, int out_size) {
    const float* x0     = (const float*)d_in[0];
    const int*   ei     = (const int*)d_in[1];
    const float* ea     = (const float*)d_in[2];
    const int*   batch  = (const int*)d_in[3];
    const float* l0Wl   = (const float*)d_in[4];
    const float* l0bl   = (const float*)d_in[5];
    const float* l0Wr   = (const float*)d_in[6];
    const float* l0br   = (const float*)d_in[7];
    const float* l0We   = (const float*)d_in[8];
    const float* l0att  = (const float*)d_in[9];
    const float* l0bias = (const float*)d_in[10];
    const float* l1Wl   = (const float*)d_in[11];
    const float* l1bl   = (const float*)d_in[12];
    const float* l1Wr   = (const float*)d_in[13];
    const float* l1br   = (const float*)d_in[14];
    const float* l1We   = (const float*)d_in[15];
    const float* l1att  = (const float*)d_in[16];
    const float* l1bias = (const float*)d_in[17];
    const float* W1     = (const float*)d_in[18];
    const float* b1     = (const float*)d_in[19];
    const float* W2     = (const float*)d_in[20];
    const float* b2     = (const float*)d_in[21];
    float* out = (float*)d_out;

    void *pcnt, *ploop, *pacc, *pden, *pg, *pgc, *pep0, *pep1;
    cudaGetSymbolAddress(&pcnt, d_cnt);
    cudaGetSymbolAddress(&ploop, d_loop);
    cudaGetSymbolAddress(&pacc, d_acc);
    cudaGetSymbolAddress(&pden, d_den);
    cudaGetSymbolAddress(&pg, d_g);
    cudaGetSymbolAddress(&pgc, d_gc);
    cudaGetSymbolAddress(&pep0, d_ep0);   // REAL device pointers for kernel args
    cudaGetSymbolAddress(&pep1, d_ep1);

    cudaMemsetAsync(pcnt, 0, NN * sizeof(float));
    cudaMemsetAsync(ploop, 0, NN * EDIM * sizeof(float));
    cudaMemsetAsync(pg, 0, GG * HID * sizeof(float));
    cudaMemsetAsync(pgc, 0, GG * sizeof(float));

    // real-edge ep for both layers + fused self-loop attr accumulation
    ep_both_k<<<4096, 128>>>(ea, ei, l0We, l1We);
    // self-loop ep (needs completed d_loop/d_cnt)
    self_ep_k<<<512, 128>>>(l0We, l1We);

    // ---- layer 0 ----
    node_proj_k<<<2048, 256>>>(x0, l0Wl, l0bl, l0Wr, l0br);
    cudaMemsetAsync(pacc, 0, (size_t)NN * HID * sizeof(float));
    cudaMemsetAsync(pden, 0, (size_t)NN * 4 * sizeof(float));
    edge_pass_k<<<2048, 256>>>(ei, l0att, (const unsigned long long*)pep0);

    // ---- layer 1 (layer-0 finalize fused into projection) ----
    node_proj_fused_k<<<2048, 256>>>(l0bias, l1Wl, l1bl, l1Wr, l1br);
    cudaMemsetAsync(pacc, 0, (size_t)NN * HID * sizeof(float));
    cudaMemsetAsync(pden, 0, (size_t)NN * 4 * sizeof(float));
    edge_pass_k<<<2048, 256>>>(ei, l1att, (const unsigned long long*)pep1);
    node_out_pool_k<<<(NN * 16 + 255) / 256, 256>>>(l1bias, batch);

    // ---- MLP ----
    mlp_k<<<GG, OUTD>>>(W1, b1, W2, b2, out);
}

// round 17
// speedup vs baseline: 8.1111x; 1.2469x over previous
#include <cuda_runtime.h>
#include <cuda_fp16.h>

#define NN 100000
#define EE 1600000
#define E2 (EE + NN)
#define NP (E2 / 2)
#define GG 64
#define HID 64
#define EDIM 16
#define OUTD 128

// ---------------- scratch (device globals; no allocation) ----------------
__device__ float d_cnt[NN];
__device__ float d_loop[NN * EDIM];
__device__ __half d_xl[NN * HID];
__device__ __half d_xr[NN * HID];
__device__ float d_acc[NN * HID];
__device__ float d_den[NN * 4];
__device__ float d_g[GG * HID];
__device__ float d_gc[GG];
// pair-interleaved ep: ep[pair*32+lane] = u64{ half2(edge0 ch2l,2l+1), half2(edge1) }
__device__ unsigned long long d_ep0[(size_t)NP * 32];
__device__ unsigned long long d_ep1[(size_t)NP * 32];

__device__ __forceinline__ void red4(float* p, float a, float b, float c, float d) {
    asm volatile("red.global.add.v4.f32 [%0], {%1,%2,%3,%4};"
                 :: "l"(p), "f"(a), "f"(b), "f"(c), "f"(d) : "memory");
}
__device__ __forceinline__ void red2(float* p, float a, float b) {
    asm volatile("red.global.add.v2.f32 [%0], {%1,%2};"
                 :: "l"(p), "f"(a), "f"(b) : "memory");
}
__device__ __forceinline__ void red1(float* p, float a) {
    asm volatile("red.global.add.f32 [%0], %1;" :: "l"(p), "f"(a) : "memory");
}
__device__ __forceinline__ unsigned h2u(float a, float b) {
    __half2 h = __floats2half2_rn(a, b);
    return *reinterpret_cast<unsigned*>(&h);
}
// packed f32x2 helpers (self_ep path)
__device__ __forceinline__ unsigned long long packdup(float a) {
    unsigned long long r;
    asm("mov.b64 %0, {%1, %1};" : "=l"(r) : "f"(a));
    return r;
}
__device__ __forceinline__ void ffma2(unsigned long long& acc, unsigned long long a,
                                      unsigned long long b) {
    asm("fma.rn.f32x2 %0, %1, %2, %3;" : "=l"(acc) : "l"(a), "l"(b), "l"(acc));
}
__device__ __forceinline__ unsigned pack_h2(unsigned long long acc) {
    float x, y;
    asm("mov.b64 {%0, %1}, %2;" : "=f"(x), "=f"(y) : "l"(acc));
    return h2u(x, y);
}

// ---------------- edge projections via tensor cores (real edges) ----------------
// One warp = one 16-edge tile. A = ea[16x16] fp16 (fp32 loads, converted),
// B = We n-tiles (fragments preloaded; 8 n-tiles x 2 layers), fp32 accumulate.
// The self-loop attr accumulation (d_loop/d_cnt) is fused: red2 on the fp32
// values already in registers. EE % 16 == 0.
__global__ __launch_bounds__(128)
void ep_tc_k(const float* __restrict__ ea, const int* __restrict__ ei,
             const float* __restrict__ We0, const float* __restrict__ We1) {
    int lane = threadIdx.x & 31;
    int g  = lane >> 2;   // 0..7
    int tg = lane & 3;    // 0..3
    int k0 = tg * 2;

    // B fragments: b[layer][ntile][reg]; col = ntile*8 + g
    unsigned rb[2][8][2];
#pragma unroll
    for (int t = 0; t < 8; t++) {
        int ch = t * 8 + g;
        rb[0][t][0] = h2u(We0[k0 * 64 + ch],       We0[(k0 + 1) * 64 + ch]);
        rb[0][t][1] = h2u(We0[(k0 + 8) * 64 + ch], We0[(k0 + 9) * 64 + ch]);
        rb[1][t][0] = h2u(We1[k0 * 64 + ch],       We1[(k0 + 1) * 64 + ch]);
        rb[1][t][1] = h2u(We1[(k0 + 8) * 64 + ch], We1[(k0 + 9) * 64 + ch]);
    }

    unsigned* ep32_0 = reinterpret_cast<unsigned*>(d_ep0);
    unsigned* ep32_1 = reinterpret_cast<unsigned*>(d_ep1);

    int wid = (blockIdx.x * blockDim.x + threadIdx.x) >> 5;
    int nwarp = (gridDim.x * blockDim.x) >> 5;

    for (int i = wid; i < EE / 16; i += nwarp) {
        int base = i * 16;
        int row1 = base + g;
        int row2 = row1 + 8;
        // A tile loads (fp32)
        float2 L0 = *reinterpret_cast<const float2*>(ea + (size_t)row1 * 16 + k0);
        float2 L1 = *reinterpret_cast<const float2*>(ea + (size_t)row2 * 16 + k0);
        float2 L2 = *reinterpret_cast<const float2*>(ea + (size_t)row1 * 16 + k0 + 8);
        float2 L3 = *reinterpret_cast<const float2*>(ea + (size_t)row2 * 16 + k0 + 8);
        int dst1 = ei[EE + row1];
        int dst2 = ei[EE + row2];

        // fused self-loop attr accumulation
        red2(d_loop + (unsigned)dst1 * 16 + k0,     L0.x, L0.y);
        red2(d_loop + (unsigned)dst2 * 16 + k0,     L1.x, L1.y);
        red2(d_loop + (unsigned)dst1 * 16 + k0 + 8, L2.x, L2.y);
        red2(d_loop + (unsigned)dst2 * 16 + k0 + 8, L3.x, L3.y);
        if (tg == 0) {
            red1(&d_cnt[dst1], 1.0f);
            red1(&d_cnt[dst2], 1.0f);
        }

        // A fragments (m16n8k16 row-major)
        unsigned ra0 = h2u(L0.x, L0.y);
        unsigned ra1 = h2u(L1.x, L1.y);
        unsigned ra2 = h2u(L2.x, L2.y);
        unsigned ra3 = h2u(L3.x, L3.y);

        unsigned par = (unsigned)(row1 & 1);
        size_t p1 = (size_t)((unsigned)row1 >> 1) * 64;   // u32 index base, pair of row1
        size_t p2 = (size_t)((unsigned)row2 >> 1) * 64;

#pragma unroll
        for (int layer = 0; layer < 2; layer++) {
            unsigned* ep32 = layer ? ep32_1 : ep32_0;
#pragma unroll
            for (int t = 0; t < 8; t++) {
                float d0, d1, d2, d3;
                float z = 0.0f;
                asm volatile(
                    "mma.sync.aligned.m16n8k16.row.col.f32.f16.f16.f32 "
                    "{%0,%1,%2,%3}, {%4,%5,%6,%7}, {%8,%9}, {%10,%11,%12,%13};"
                    : "=f"(d0), "=f"(d1), "=f"(d2), "=f"(d3)
                    : "r"(ra0), "r"(ra1), "r"(ra2), "r"(ra3),
                      "r"(rb[layer][t][0]), "r"(rb[layer][t][1]),
                      "f"(z), "f"(z), "f"(z), "f"(z));
                unsigned cp = (unsigned)(t * 4 + tg);     // channel-pair index 0..31
                ep32[p1 + cp * 2 + par] = h2u(d0, d1);    // edge row1
                ep32[p2 + cp * 2 + par] = h2u(d2, d3);    // edge row2
            }
        }
    }
}

// ---------------- self-loop edge projections (needs completed d_loop/d_cnt) ----------------
__global__ void self_ep_k(const float* __restrict__ We0, const float* __restrict__ We1) {
    const unsigned F = 0xffffffffu;
    int lane = threadIdx.x & 31;
    unsigned long long w0[EDIM], w1[EDIM];
    const unsigned long long* We0q = reinterpret_cast<const unsigned long long*>(We0);
    const unsigned long long* We1q = reinterpret_cast<const unsigned long long*>(We1);
#pragma unroll
    for (int k = 0; k < EDIM; k++) {
        w0[k] = We0q[k * 32 + lane];
        w1[k] = We1q[k * 32 + lane];
    }
    int wid = (blockIdx.x * blockDim.x + threadIdx.x) >> 5;
    int nwarp = (gridDim.x * blockDim.x) >> 5;

    for (int i = wid; i < NN / 2; i += nwarp) {
        int n0 = 2 * i;
        int n = n0 + (lane >> 4);
        float av = d_loop[(unsigned)n0 * EDIM + lane] / fmaxf(d_cnt[n], 1.0f);
        unsigned long long a00 = 0ull, a01 = 0ull, a10 = 0ull, a11 = 0ull;
#pragma unroll
        for (int k = 0; k < EDIM; k++) {
            unsigned long long p0 = packdup(__shfl_sync(F, av, k));
            unsigned long long p1 = packdup(__shfl_sync(F, av, k + 16));
            ffma2(a00, p0, w0[k]);
            ffma2(a01, p0, w1[k]);
            ffma2(a10, p1, w0[k]);
            ffma2(a11, p1, w1[k]);
        }
        unsigned long long v0, v1;
        asm("mov.b64 %0, {%1,%2};" : "=l"(v0) : "r"(pack_h2(a00)), "r"(pack_h2(a10)));
        asm("mov.b64 %0, {%1,%2};" : "=l"(v1) : "r"(pack_h2(a01)), "r"(pack_h2(a11)));
        size_t pi = (size_t)(EE / 2) + i;
        d_ep0[pi * 32 + lane] = v0;
        d_ep1[pi * 32 + lane] = v1;
    }
}

// ---------------- node projections (layer 0), 8-row register blocking ----------------
__global__ void node_proj_k(const float* __restrict__ x,
                            const float* __restrict__ Wl, const float* __restrict__ bl,
                            const float* __restrict__ Wr, const float* __restrict__ br) {
    __shared__ float sWl[64 * 64];
    __shared__ float sWr[64 * 64];
    __shared__ float sx[32 * 64];
    for (int i = threadIdx.x; i < 64 * 16; i += blockDim.x) {
        reinterpret_cast<float4*>(sWl)[i] = reinterpret_cast<const float4*>(Wl)[i];
        reinterpret_cast<float4*>(sWr)[i] = reinterpret_cast<const float4*>(Wr)[i];
    }
    int c  = threadIdx.x & 63;
    int rl = threadIdx.x >> 6;
    float blc = bl[c], brc = br[c];
    for (int base = blockIdx.x * 32; base < NN; base += gridDim.x * 32) {
        __syncthreads();
        for (int i = threadIdx.x; i < 32 * 16; i += 256) {
            int r = base + (i >> 4);
            reinterpret_cast<float4*>(sx)[i] = (r < NN)
                ? reinterpret_cast<const float4*>(x)[(size_t)r * 16 + (i & 15)]
                : make_float4(0.f, 0.f, 0.f, 0.f);
        }
        __syncthreads();
        float s[8], t[8];
#pragma unroll
        for (int j = 0; j < 8; j++) { s[j] = blc; t[j] = brc; }
        const float* xrow = sx + rl * 8 * 64;
#pragma unroll
        for (int k = 0; k < 64; k++) {
            float wl = sWl[k * 64 + c];
            float wr = sWr[k * 64 + c];
#pragma unroll
            for (int j = 0; j < 8; j++) {
                float xv = xrow[j * 64 + k];
                s[j] += xv * wl;
                t[j] += xv * wr;
            }
        }
        int r0 = base + rl * 8;
#pragma unroll
        for (int j = 0; j < 8; j++) {
            if (r0 + j < NN) {
                d_xl[(size_t)(r0 + j) * 64 + c] = __float2half(s[j]);
                d_xr[(size_t)(r0 + j) * 64 + c] = __float2half(t[j]);
            }
        }
    }
}

// ---------------- node projection (layer 1): fuses layer-0 finalize, 8-row blocking ----------------
__global__ void node_proj_fused_k(const float* __restrict__ bias0,
                                  const float* __restrict__ Wl, const float* __restrict__ bl,
                                  const float* __restrict__ Wr, const float* __restrict__ br) {
    __shared__ float sWl[64 * 64];
    __shared__ float sWr[64 * 64];
    __shared__ float sx[32 * 64];
    for (int i = threadIdx.x; i < 64 * 16; i += blockDim.x) {
        reinterpret_cast<float4*>(sWl)[i] = reinterpret_cast<const float4*>(Wl)[i];
        reinterpret_cast<float4*>(sWr)[i] = reinterpret_cast<const float4*>(Wr)[i];
    }
    int c  = threadIdx.x & 63;
    int rl = threadIdx.x >> 6;
    float blc = bl[c], brc = br[c];
    for (int base = blockIdx.x * 32; base < NN; base += gridDim.x * 32) {
        __syncthreads();
        for (int i = threadIdx.x; i < 32 * 16; i += 256) {
            int r = base + (i >> 4);
            int part = i & 15;
            float4 v = make_float4(0.f, 0.f, 0.f, 0.f);
            if (r < NN) {
                float inv = 1.0f / d_den[r * 4 + (part >> 2)];
                float4 a = reinterpret_cast<const float4*>(d_acc)[(size_t)r * 16 + part];
                float4 b = reinterpret_cast<const float4*>(bias0)[part];
                v.x = fmaxf(a.x * inv + b.x, 0.0f);
                v.y = fmaxf(a.y * inv + b.y, 0.0f);
                v.z = fmaxf(a.z * inv + b.z, 0.0f);
                v.w = fmaxf(a.w * inv + b.w, 0.0f);
            }
            reinterpret_cast<float4*>(sx)[i] = v;
        }
        __syncthreads();
        float s[8], t[8];
#pragma unroll
        for (int j = 0; j < 8; j++) { s[j] = blc; t[j] = brc; }
        const float* xrow = sx + rl * 8 * 64;
#pragma unroll
        for (int k = 0; k < 64; k++) {
            float wl = sWl[k * 64 + c];
            float wr = sWr[k * 64 + c];
#pragma unroll
            for (int j = 0; j < 8; j++) {
                float xv = xrow[j * 64 + k];
                s[j] += xv * wl;
                t[j] += xv * wr;
            }
        }
        int r0 = base + rl * 8;
#pragma unroll
        for (int j = 0; j < 8; j++) {
            if (r0 + j < NN) {
                d_xl[(size_t)(r0 + j) * 64 + c] = __float2half(s[j]);
                d_xr[(size_t)(r0 + j) * 64 + c] = __float2half(t[j]);
            }
        }
    }
}

// ---------------- edge pass: 8 edges per warp iteration ----------------
__global__ __launch_bounds__(256)
void edge_pass_k(const int* __restrict__ ei, const float* __restrict__ att,
                 const unsigned long long* __restrict__ ep) {
    const unsigned F = 0xffffffffu;
    unsigned lane = threadIdx.x & 31;
    float2 at = reinterpret_cast<const float2*>(att)[lane];

    int wid = (blockIdx.x * blockDim.x + threadIdx.x) >> 5;
    int nwarp = (gridDim.x * blockDim.x) >> 5;
    const __half2* xl2p = reinterpret_cast<const __half2*>(d_xl);
    const __half2* xr2p = reinterpret_cast<const __half2*>(d_xr);

    for (int i = wid; i < E2 / 8; i += nwarp) {
        int e0 = 8 * i;
        int s[8], d[8];
        if (e0 < EE) {
            int4 sa = *reinterpret_cast<const int4*>(ei + e0);
            int4 sb = *reinterpret_cast<const int4*>(ei + e0 + 4);
            int4 da = *reinterpret_cast<const int4*>(ei + EE + e0);
            int4 db = *reinterpret_cast<const int4*>(ei + EE + e0 + 4);
            s[0]=sa.x; s[1]=sa.y; s[2]=sa.z; s[3]=sa.w;
            s[4]=sb.x; s[5]=sb.y; s[6]=sb.z; s[7]=sb.w;
            d[0]=da.x; d[1]=da.y; d[2]=da.z; d[3]=da.w;
            d[4]=db.x; d[5]=db.y; d[6]=db.z; d[7]=db.w;
        } else {
            int n = e0 - EE;
#pragma unroll
            for (int j = 0; j < 8; j++) { s[j] = n + j; d[j] = n + j; }
        }
        float2 epv[8];
#pragma unroll
        for (int j = 0; j < 4; j++) {
            unsigned long long q = ep[(size_t)(4 * i + j) * 32 + lane];
            unsigned ha, hb;
            asm("mov.b64 {%0,%1}, %2;" : "=r"(ha), "=r"(hb) : "l"(q));
            epv[2 * j]     = __half22float2(*reinterpret_cast<__half2*>(&ha));
            epv[2 * j + 1] = __half22float2(*reinterpret_cast<__half2*>(&hb));
        }
        float2 xl[8], xr[8];
#pragma unroll
        for (int j = 0; j < 8; j++) {
            xl[j] = __half22float2(xl2p[(unsigned)s[j] * 32 + lane]);
            xr[j] = __half22float2(xr2p[(unsigned)d[j] * 32 + lane]);
        }
        float sc[8];
#pragma unroll
        for (int j = 0; j < 8; j++) {
            float mx = xl[j].x + xr[j].x + epv[j].x;
            float my = xl[j].y + xr[j].y + epv[j].y;
            mx = (mx > 0.f) ? mx : 0.2f * mx;
            my = (my > 0.f) ? my : 0.2f * my;
            sc[j] = mx * at.x + my * at.y;
        }
#pragma unroll
        for (int j = 0; j < 8; j++) sc[j] += __shfl_xor_sync(F, sc[j], 1);
#pragma unroll
        for (int j = 0; j < 8; j++) sc[j] += __shfl_xor_sync(F, sc[j], 2);
#pragma unroll
        for (int j = 0; j < 8; j++) sc[j] += __shfl_xor_sync(F, sc[j], 4);
        float z[8];
#pragma unroll
        for (int j = 0; j < 8; j++) z[j] = __expf(sc[j]);   // softmax without max-shift

#pragma unroll
        for (int j = 0; j < 8; j++)
            red2(d_acc + (unsigned)d[j] * 64 + 2 * lane, z[j] * xl[j].x, z[j] * xl[j].y);
        if ((lane & 7) == 0) {
            unsigned h = lane >> 3;
#pragma unroll
            for (int j = 0; j < 8; j++)
                atomicAdd(&d_den[(unsigned)d[j] * 4 + h], z[j]);
        }
    }
}

// ---------------- finalize layer 1 fused with global mean pool ----------------
__global__ void node_out_pool_k(const float* __restrict__ bias, const int* __restrict__ batch) {
    int t = blockIdx.x * blockDim.x + threadIdx.x;
    if (t >= NN * 16) return;
    int node = t >> 4;
    int part = t & 15;
    float inv = 1.0f / d_den[node * 4 + (part >> 2)];
    float4 a = reinterpret_cast<const float4*>(d_acc)[t];
    float4 b = reinterpret_cast<const float4*>(bias)[part];
    float vx = fmaxf(a.x * inv + b.x, 0.0f);
    float vy = fmaxf(a.y * inv + b.y, 0.0f);
    float vz = fmaxf(a.z * inv + b.z, 0.0f);
    float vw = fmaxf(a.w * inv + b.w, 0.0f);
    int g = batch[node];
    red4(d_g + g * 64 + part * 4, vx, vy, vz, vw);
    if (part == 0) atomicAdd(&d_gc[g], 1.0f);
}

// ---------------- MLP head ----------------
__global__ void mlp_k(const float* __restrict__ W1, const float* __restrict__ b1,
                      const float* __restrict__ W2, const float* __restrict__ b2,
                      float* __restrict__ out) {
    __shared__ float gx[64];
    __shared__ float hh[128];
    int g = blockIdx.x;
    int t = threadIdx.x;
    if (t < 64) gx[t] = d_g[g * 64 + t] / fmaxf(d_gc[g], 1.0f);
    __syncthreads();
    float s = b1[t];
#pragma unroll
    for (int k = 0; k < 64; k++) s += gx[k] * W1[k * 128 + t];
    hh[t] = fmaxf(s, 0.0f);
    __syncthreads();
    float o = b2[t];
#pragma unroll
    for (int k = 0; k < 128; k++) o += hh[k] * W2[k * 128 + t];
    out[g * 128 + t] = o;
}

// ---------------- launch (single stream) ----------------
extern "C" void kernel_launch(void* const* d_in, const int* in_sizes, int n_in,
                              void* d_out, int out_size) {
    const float* x0     = (const float*)d_in[0];
    const int*   ei     = (const int*)d_in[1];
    const float* ea     = (const float*)d_in[2];
    const int*   batch  = (const int*)d_in[3];
    const float* l0Wl   = (const float*)d_in[4];
    const float* l0bl   = (const float*)d_in[5];
    const float* l0Wr   = (const float*)d_in[6];
    const float* l0br   = (const float*)d_in[7];
    const float* l0We   = (const float*)d_in[8];
    const float* l0att  = (const float*)d_in[9];
    const float* l0bias = (const float*)d_in[10];
    const float* l1Wl   = (const float*)d_in[11];
    const float* l1bl   = (const float*)d_in[12];
    const float* l1Wr   = (const float*)d_in[13];
    const float* l1br   = (const float*)d_in[14];
    const float* l1We   = (const float*)d_in[15];
    const float* l1att  = (const float*)d_in[16];
    const float* l1bias = (const float*)d_in[17];
    const float* W1     = (const float*)d_in[18];
    const float* b1     = (const float*)d_in[19];
    const float* W2     = (const float*)d_in[20];
    const float* b2     = (const float*)d_in[21];
    float* out = (float*)d_out;

    void *pcnt, *ploop, *pacc, *pden, *pg, *pgc, *pep0, *pep1;
    cudaGetSymbolAddress(&pcnt, d_cnt);
    cudaGetSymbolAddress(&ploop, d_loop);
    cudaGetSymbolAddress(&pacc, d_acc);
    cudaGetSymbolAddress(&pden, d_den);
    cudaGetSymbolAddress(&pg, d_g);
    cudaGetSymbolAddress(&pgc, d_gc);
    cudaGetSymbolAddress(&pep0, d_ep0);   // REAL device pointers for kernel args
    cudaGetSymbolAddress(&pep1, d_ep1);

    cudaMemsetAsync(pcnt, 0, NN * sizeof(float));
    cudaMemsetAsync(ploop, 0, NN * EDIM * sizeof(float));
    cudaMemsetAsync(pg, 0, GG * HID * sizeof(float));
    cudaMemsetAsync(pgc, 0, GG * sizeof(float));

    // real-edge ep for both layers on tensor cores + fused self-loop attr accumulation
    ep_tc_k<<<2048, 128>>>(ea, ei, l0We, l1We);
    // self-loop ep (needs completed d_loop/d_cnt)
    self_ep_k<<<512, 128>>>(l0We, l1We);

    // ---- layer 0 ----
    node_proj_k<<<2048, 256>>>(x0, l0Wl, l0bl, l0Wr, l0br);
    cudaMemsetAsync(pacc, 0, (size_t)NN * HID * sizeof(float));
    cudaMemsetAsync(pden, 0, (size_t)NN * 4 * sizeof(float));
    edge_pass_k<<<2048, 256>>>(ei, l0att, (const unsigned long long*)pep0);

    // ---- layer 1 (layer-0 finalize fused into projection) ----
    node_proj_fused_k<<<2048, 256>>>(l0bias, l1Wl, l1bl, l1Wr, l1br);
    cudaMemsetAsync(pacc, 0, (size_t)NN * HID * sizeof(float));
    cudaMemsetAsync(pden, 0, (size_t)NN * 4 * sizeof(float));
    edge_pass_k<<<2048, 256>>>(ei, l1att, (const unsigned long long*)pep1);
    node_out_pool_k<<<(NN * 16 + 255) / 256, 256>>>(l1bias, batch);

    // ---- MLP ----
    mlp_k<<<GG, OUTD>>>(W1, b1, W2, b2, out);
}